// round 10
// baseline (speedup 1.0000x reference)
#include <cuda_runtime.h>
#include <cuda_fp16.h>
#include <math.h>
#include <stdint.h>

#define BB 4
#define SS 1024
#define EE 1024
#define HH 16
#define DH 64
#define ROWS (BB*SS)
#define LN_EPS 1e-5f

typedef unsigned short u16;
typedef unsigned int   u32;
typedef unsigned long long u64;

#define LO_SCALE 2048.0f
#define LO_INV   (1.0f/2048.0f)

// ---------------- scratch (device globals; no allocation allowed) ----------------
__device__ u16 g_h_hi [ROWS*EE],    g_h_lo [ROWS*EE];
__device__ u16 g_qkv_hi[ROWS*3*EE], g_qkv_lo[ROWS*3*EE];
__device__ u16 g_vt_hi[BB*HH*DH*SS], g_vt_lo[BB*HH*DH*SS];
__device__ u16 g_p_hi[(long long)BB*HH*SS*SS], g_p_lo[(long long)BB*HH*SS*SS];
__device__ u16 g_att_hi[ROWS*EE],   g_att_lo[ROWS*EE];
__device__ float g_x1[ROWS*EE];
__device__ u16 g_h2_hi[ROWS*EE],    g_h2_lo[ROWS*EE];
__device__ u16 g_fc_hi[ROWS*4*EE],  g_fc_lo[ROWS*4*EE];
__device__ u16 g_win_hi [3*EE*EE],  g_win_lo [3*EE*EE];
__device__ u16 g_wout_hi[EE*EE],    g_wout_lo[EE*EE];
__device__ u16 g_wfc_hi [4*EE*EE],  g_wfc_lo [4*EE*EE];
__device__ u16 g_wpr_hi [4*EE*EE],  g_wpr_lo [4*EE*EE];

// ---------------- helpers (fp16 split: x = hi + lo/2048) ----------------
__device__ __forceinline__ float h2f(u16 u){ return __half2float(__ushort_as_half(u)); }
__device__ __forceinline__ u16 f2h(float f){ return __half_as_ushort(__float2half_rn(f)); }
__device__ __forceinline__ u32 smem_u32(const void* p){
    u32 a; asm("{ .reg .u64 t; cvta.to.shared.u64 t, %1; cvt.u32.u64 %0, t; }" : "=r"(a) : "l"(p));
    return a;
}
__device__ __forceinline__ void cp16(u32 dst, const void* src){
    asm volatile("cp.async.cg.shared.global [%0], [%1], 16;\n" :: "r"(dst), "l"(src));
}
#define CP_COMMIT() asm volatile("cp.async.commit_group;\n" ::: "memory")
#define CP_WAIT0()  asm volatile("cp.async.wait_group 0;\n" ::: "memory")
#define CP_WAIT1()  asm volatile("cp.async.wait_group 1;\n" ::: "memory")

__device__ __forceinline__ void ldmx4(u32& r0, u32& r1, u32& r2, u32& r3, u32 addr){
    asm volatile("ldmatrix.sync.aligned.m8n8.x4.shared.b16 {%0,%1,%2,%3}, [%4];"
        : "=r"(r0),"=r"(r1),"=r"(r2),"=r"(r3) : "r"(addr));
}
__device__ __forceinline__ void ldmx2(u32& r0, u32& r1, u32 addr){
    asm volatile("ldmatrix.sync.aligned.m8n8.x2.shared.b16 {%0,%1}, [%2];"
        : "=r"(r0),"=r"(r1) : "r"(addr));
}
// f32-accumulator fp16 HMMA
__device__ __forceinline__ void mma16816(float* c, const u32* a, const u32* b){
    asm volatile("mma.sync.aligned.m16n8k16.row.col.f32.f16.f16.f32 "
        "{%0,%1,%2,%3}, {%4,%5,%6,%7}, {%8,%9}, {%0,%1,%2,%3};"
        : "+f"(c[0]),"+f"(c[1]),"+f"(c[2]),"+f"(c[3])
        : "r"(a[0]),"r"(a[1]),"r"(a[2]),"r"(a[3]), "r"(b[0]),"r"(b[1]));
}
// f16-accumulator fp16 HMMA (correction products)
__device__ __forceinline__ void mma16816h(u32* c, const u32* a, const u32* b){
    asm volatile("mma.sync.aligned.m16n8k16.row.col.f16.f16.f16.f16 "
        "{%0,%1}, {%2,%3,%4,%5}, {%6,%7}, {%0,%1};"
        : "+r"(c[0]),"+r"(c[1])
        : "r"(a[0]),"r"(a[1]),"r"(a[2]),"r"(a[3]), "r"(b[0]),"r"(b[1]));
}

// flags
#define FLAG_GELU   1
#define FLAG_CAUSAL 2
#define FLAG_CLIPK  4
#define FLAG_SPLIT  8

#define TM 128
#define KT 64
#define LDS_ROW 72          // 64 k-elems + 8 pad (144B row stride; conflict-free ldmatrix)

// ---------------- HMMA fp16-split GEMM ----------------
// C = alpha * A·B^T (+bias/+resid/gelu/split).  A [M,K] K-major hi/lo; B [N,K] K-major hi/lo.
// hi·hi in f32 acc; hi·lo + lo·hi (lo pre-scaled x2048) in f16 acc, merged /2048.
template<int TN>
__global__ __launch_bounds__(256, 1)
void mma_gemm(const u16* __restrict__ Ahi, const u16* __restrict__ Alo, int lda,
              long long sAb, long long sAh,
              const u16* __restrict__ Bhi, const u16* __restrict__ Blo, int ldb,
              long long sBb, long long sBh,
              float* __restrict__ Cf, u16* __restrict__ Chi, u16* __restrict__ Clo, int ldc,
              long long sCb, long long sCh,
              const float* __restrict__ bias, const float* __restrict__ resid,
              int K, int Hdiv, float alpha, int flags)
{
    constexpr int WM = (TN == 128) ? 2 : 4;      // warp grid m
    constexpr int WN = 8 / WM;                   // warp grid n
    constexpr int MT = TM / (WM * 16);           // m16 tiles per warp
    constexpr int NT = TN / (WN * 8);            // n8 tiles per warp
    constexpr int OA = TM * LDS_ROW;             // elems per A buf
    constexpr int OB = TN * LDS_ROW;
    constexpr int STG = 2*OA + 2*OB;             // elems per stage (Ahi,Alo,Bhi,Blo)

    int m0 = blockIdx.y * TM;
    int n0 = blockIdx.x * TN;
    if ((flags & FLAG_CAUSAL) && n0 >= m0 + TM) return;   // fully masked tile

    int z  = blockIdx.z;
    int bb = z / Hdiv, hh = z % Hdiv;
    const u16* Ah = Ahi + bb*sAb + hh*sAh + (long long)m0*lda;
    const u16* Al = Alo + bb*sAb + hh*sAh + (long long)m0*lda;
    const u16* Bh = Bhi + bb*sBb + hh*sBh + (long long)n0*ldb;
    const u16* Bl = Blo + bb*sBb + hh*sBh + (long long)n0*ldb;

    int Keff = K;
    if (flags & FLAG_CLIPK) { int lim = m0 + TM; Keff = (lim < K) ? lim : K; }
    int T = Keff / KT;

    extern __shared__ __align__(128) u16 sm[];
    u32 sbase = smem_u32(sm);
    int tid = threadIdx.x;
    int lane = tid & 31, wid = tid >> 5;
    int warp_m = wid / WN, warp_n = wid % WN;

    auto load_tile = [&](int s, int k0){
        u32 base = sbase + s * STG * 2;
        for (int e = tid; e < TM*8; e += 256) {
            int r = e >> 3, c = e & 7;
            u32 off = (u32)(r*LDS_ROW*2 + c*16);
            long long g = (long long)r*lda + k0 + c*8;
            cp16(base + off,          Ah + g);
            cp16(base + OA*2 + off,   Al + g);
        }
        for (int e = tid; e < TN*8; e += 256) {
            int r = e >> 3, c = e & 7;
            u32 off = (u32)(r*LDS_ROW*2 + c*16);
            long long g = (long long)r*ldb + k0 + c*8;
            cp16(base + 4*OA + off,         Bh + g);
            cp16(base + 4*OA + 2*OB + off,  Bl + g);
        }
    };

    float acc[MT][NT][4];
    u32  acch[MT][NT][2];
    #pragma unroll
    for (int i = 0; i < MT; i++)
        #pragma unroll
        for (int j = 0; j < NT; j++) {
            #pragma unroll
            for (int q = 0; q < 4; q++) acc[i][j][q] = 0.f;
            acch[i][j][0] = 0u; acch[i][j][1] = 0u;
        }

    load_tile(0, 0); CP_COMMIT();

    for (int t = 0; t < T; ++t) {
        if (t + 1 < T) { load_tile((t+1) & 1, (t+1)*KT); CP_COMMIT(); CP_WAIT1(); }
        else           { CP_WAIT0(); }
        __syncthreads();

        int s = t & 1;
        u32 aHiB = sbase + s*STG*2;
        u32 aLoB = aHiB + OA*2;
        u32 bHiB = aHiB + 4*OA;
        u32 bLoB = bHiB + OB*2;

        #pragma unroll
        for (int ks = 0; ks < 4; ks++) {
            u32 aHi[MT][4], aLo[MT][4], bHi[NT][2], bLo[NT][2];
            #pragma unroll
            for (int mt = 0; mt < MT; mt++) {
                int row = warp_m*MT*16 + mt*16 + (lane & 15);
                u32 off = (u32)(row*LDS_ROW*2 + ks*32 + (lane >> 4)*16);
                ldmx4(aHi[mt][0], aHi[mt][1], aHi[mt][2], aHi[mt][3], aHiB + off);
                ldmx4(aLo[mt][0], aLo[mt][1], aLo[mt][2], aLo[mt][3], aLoB + off);
            }
            #pragma unroll
            for (int nt = 0; nt < NT; nt++) {
                int row = warp_n*NT*8 + nt*8 + (lane & 7);
                u32 off = (u32)(row*LDS_ROW*2 + ks*32 + ((lane >> 3) & 1)*16);
                ldmx2(bHi[nt][0], bHi[nt][1], bHiB + off);
                ldmx2(bLo[nt][0], bLo[nt][1], bLoB + off);
            }
            #pragma unroll
            for (int mt = 0; mt < MT; mt++)
                #pragma unroll
                for (int nt = 0; nt < NT; nt++) {
                    mma16816 (acc[mt][nt],  aHi[mt], bHi[nt]);   // main, f32 acc
                    mma16816h(acch[mt][nt], aHi[mt], bLo[nt]);   // corrections, f16 acc
                    mma16816h(acch[mt][nt], aLo[mt], bHi[nt]);
                }
        }
        __syncthreads();
    }

    // ---- epilogue (packed stores: lanes own (n, n+1) pairs) ----
    long long cb = bb*sCb + hh*sCh;
    #pragma unroll
    for (int mt = 0; mt < MT; mt++) {
        #pragma unroll
        for (int nt = 0; nt < NT; nt++) {
            int rr = m0 + warp_m*MT*16 + mt*16 + (lane >> 2);
            int nn = n0 + warp_n*NT*8 + nt*8 + (lane & 3)*2;
            #pragma unroll
            for (int half = 0; half < 2; half++) {
                int m = rr + half*8;
                long long crow = cb + (long long)m*ldc;
                half2 hc = *reinterpret_cast<half2*>(&acch[mt][nt][half]);
                float corr[2] = { __low2float(hc), __high2float(hc) };
                float v[2];
                #pragma unroll
                for (int j = 0; j < 2; j++) {
                    float vv = (acc[mt][nt][half*2 + j] + corr[j]*LO_INV) * alpha;
                    int n = nn + j;
                    if (bias)  vv += bias[n];
                    if (resid) vv += resid[crow + n];
                    if (flags & FLAG_GELU) {
                        float tg = tanhf(0.7978845608028654f * (vv + 0.044715f*vv*vv*vv));
                        vv = 0.5f * vv * (1.f + tg);
                    }
                    v[j] = vv;
                }
                if (flags & FLAG_SPLIT) {
                    u16 h0 = f2h(v[0]), h1 = f2h(v[1]);
                    u16 l0 = f2h((v[0] - h2f(h0))*LO_SCALE), l1 = f2h((v[1] - h2f(h1))*LO_SCALE);
                    *reinterpret_cast<u32*>(Chi + crow + nn) = (u32)h0 | ((u32)h1 << 16);
                    *reinterpret_cast<u32*>(Clo + crow + nn) = (u32)l0 | ((u32)l1 << 16);
                } else {
                    *reinterpret_cast<float2*>(Cf + crow + nn) = make_float2(v[0], v[1]);
                }
            }
        }
    }
}

// ---------------- LayerNorm -> fp16 split ----------------
__global__ void ln_split_kernel(const float* __restrict__ x,
                                const float* __restrict__ g,
                                const float* __restrict__ b,
                                u16* __restrict__ ohi, u16* __restrict__ olo)
{
    long long row = blockIdx.x;
    const float* xr = x + row * EE;
    __shared__ float red[256];
    int tid = threadIdx.x;

    float s = 0.f;
    for (int c = tid; c < EE; c += 256) s += xr[c];
    red[tid] = s; __syncthreads();
    for (int st = 128; st > 0; st >>= 1){ if (tid < st) red[tid] += red[tid+st]; __syncthreads(); }
    float mu = red[0] * (1.f/EE); __syncthreads();

    float v = 0.f;
    for (int c = tid; c < EE; c += 256){ float d = xr[c]-mu; v += d*d; }
    red[tid] = v; __syncthreads();
    for (int st = 128; st > 0; st >>= 1){ if (tid < st) red[tid] += red[tid+st]; __syncthreads(); }
    float inv = rsqrtf(red[0]*(1.f/EE) + LN_EPS); __syncthreads();

    for (int c = tid; c < EE; c += 256) {
        float o = (xr[c]-mu)*inv*g[c] + b[c];
        u16 hi = f2h(o);
        ohi[row*EE + c] = hi;
        olo[row*EE + c] = f2h((o - h2f(hi))*LO_SCALE);
    }
}

// ---------------- split f32 -> fp16 hi/lo ----------------
__global__ void split_kernel(const float* __restrict__ src, u16* __restrict__ hi,
                             u16* __restrict__ lo, long long n)
{
    long long i = ((long long)blockIdx.x * 256 + threadIdx.x) * 4;
    if (i >= n) return;
    float4 v = *reinterpret_cast<const float4*>(src + i);
    float vv[4] = {v.x, v.y, v.z, v.w};
    u16 h[4], l[4];
    #pragma unroll
    for (int j = 0; j < 4; j++){ h[j] = f2h(vv[j]); l[j] = f2h((vv[j] - h2f(h[j]))*LO_SCALE); }
    *reinterpret_cast<u64*>(hi + i) = *(u64*)h;
    *reinterpret_cast<u64*>(lo + i) = *(u64*)l;
}

// ---------------- transpose V: qkv[b,s, 2E + h*64 + d] -> vt[(b,h), d, s] ----------------
__global__ void transpose_v(const u16* __restrict__ qh, const u16* __restrict__ ql,
                            u16* __restrict__ vth, u16* __restrict__ vtl)
{
    __shared__ u16 th[32][33], tl[32][33];
    int bh = blockIdx.z; int b = bh >> 4, h = bh & 15;
    int s0 = blockIdx.x * 32, d0 = blockIdx.y * 32;
    int tx = threadIdx.x, ty = threadIdx.y;
    #pragma unroll
    for (int i = 0; i < 4; i++) {
        int s = s0 + ty + i*8;
        long long src = ((long long)(b*SS + s))*(3*EE) + 2*EE + h*DH + d0 + tx;
        th[ty + i*8][tx] = qh[src];
        tl[ty + i*8][tx] = ql[src];
    }
    __syncthreads();
    #pragma unroll
    for (int i = 0; i < 4; i++) {
        int d = d0 + ty + i*8;
        long long dst = ((long long)(bh*DH + d))*SS + s0 + tx;
        vth[dst] = th[tx][ty + i*8];
        vtl[dst] = tl[tx][ty + i*8];
    }
}

// ---------------- fused causal softmax (all heads) + att_weights ----------------
// One block per (b, q). Probs written only to k < (q/128+1)*128 (what PV reads).
__global__ void softmax_attw(u16* __restrict__ ph, u16* __restrict__ pl,
                             float* __restrict__ outw)
{
    int bq = blockIdx.x;            // b*SS + q
    int b = bq >> 10, q = bq & (SS-1);
    int Lw = ((q >> 7) + 1) << 7;   // write length (multiple of 128)
    int tid = threadIdx.x;          // 256
    __shared__ float row[SS];
    __shared__ float red[256];
    float aw[4] = {0.f, 0.f, 0.f, 0.f};

    for (int h = 0; h < HH; h++) {
        long long base = (((long long)(b*HH + h)) << 20) | ((long long)q << 10);
        float mx = -1e30f;
        for (int c = tid; c <= q; c += 256) {
            float v = h2f(ph[base+c]) + h2f(pl[base+c])*LO_INV;
            row[c] = v;
            mx = fmaxf(mx, v);
        }
        red[tid] = mx; __syncthreads();
        for (int st = 128; st > 0; st >>= 1){ if (tid < st) red[tid] = fmaxf(red[tid], red[tid+st]); __syncthreads(); }
        mx = red[0]; __syncthreads();

        float sum = 0.f;
        for (int c = tid; c <= q; c += 256){ float e = __expf(row[c]-mx); row[c] = e; sum += e; }
        red[tid] = sum; __syncthreads();
        for (int st = 128; st > 0; st >>= 1){ if (tid < st) red[tid] += red[tid+st]; __syncthreads(); }
        float inv = 1.f / red[0]; __syncthreads();

        for (int c = tid; c < Lw; c += 256) {
            float p = (c <= q) ? row[c]*inv : 0.f;
            u16 hi = f2h(p);
            ph[base+c] = hi;
            pl[base+c] = f2h((p - h2f(hi))*LO_SCALE);
            aw[c >> 8] += p;
        }
    }
    long long ob = ((long long)bq) << 10;
    #pragma unroll
    for (int i = 0; i < 4; i++) {
        int c = tid + 256*i;
        outw[ob + c] = (c <= q) ? aw[i]*(1.f/HH) : 0.f;
    }
}

// ---------------- launch ----------------
extern "C" void kernel_launch(void* const* d_in, const int* in_sizes, int n_in,
                              void* d_out, int out_size)
{
    const float* x      = (const float*)d_in[0];
    const float* ln1_g  = (const float*)d_in[2];
    const float* ln1_b  = (const float*)d_in[3];
    const float* ln2_g  = (const float*)d_in[4];
    const float* ln2_b  = (const float*)d_in[5];
    const float* w_in   = (const float*)d_in[6];
    const float* b_in   = (const float*)d_in[7];
    const float* w_out  = (const float*)d_in[8];
    const float* b_out  = (const float*)d_in[9];
    const float* w_fc   = (const float*)d_in[10];
    const float* b_fc   = (const float*)d_in[11];
    const float* w_proj = (const float*)d_in[12];
    const float* b_proj = (const float*)d_in[13];

    float* out_x = (float*)d_out;
    float* out_w = (float*)d_out + (long long)ROWS*EE;

    u16 *h_hi,*h_lo,*qkv_hi,*qkv_lo,*vt_hi,*vt_lo,*p_hi,*p_lo,*att_hi,*att_lo,*h2_hi,*h2_lo,*fc_hi,*fc_lo;
    u16 *win_hi,*win_lo,*wout_hi,*wout_lo,*wfc_hi,*wfc_lo,*wpr_hi,*wpr_lo;
    float *x1;
    cudaGetSymbolAddress((void**)&h_hi, g_h_hi);     cudaGetSymbolAddress((void**)&h_lo, g_h_lo);
    cudaGetSymbolAddress((void**)&qkv_hi, g_qkv_hi); cudaGetSymbolAddress((void**)&qkv_lo, g_qkv_lo);
    cudaGetSymbolAddress((void**)&vt_hi, g_vt_hi);   cudaGetSymbolAddress((void**)&vt_lo, g_vt_lo);
    cudaGetSymbolAddress((void**)&p_hi, g_p_hi);     cudaGetSymbolAddress((void**)&p_lo, g_p_lo);
    cudaGetSymbolAddress((void**)&att_hi, g_att_hi); cudaGetSymbolAddress((void**)&att_lo, g_att_lo);
    cudaGetSymbolAddress((void**)&x1, g_x1);
    cudaGetSymbolAddress((void**)&h2_hi, g_h2_hi);   cudaGetSymbolAddress((void**)&h2_lo, g_h2_lo);
    cudaGetSymbolAddress((void**)&fc_hi, g_fc_hi);   cudaGetSymbolAddress((void**)&fc_lo, g_fc_lo);
    cudaGetSymbolAddress((void**)&win_hi, g_win_hi); cudaGetSymbolAddress((void**)&win_lo, g_win_lo);
    cudaGetSymbolAddress((void**)&wout_hi, g_wout_hi); cudaGetSymbolAddress((void**)&wout_lo, g_wout_lo);
    cudaGetSymbolAddress((void**)&wfc_hi, g_wfc_hi); cudaGetSymbolAddress((void**)&wfc_lo, g_wfc_lo);
    cudaGetSymbolAddress((void**)&wpr_hi, g_wpr_hi); cudaGetSymbolAddress((void**)&wpr_lo, g_wpr_lo);

    const int SM128 = 2 * (2*TM*LDS_ROW + 2*128*LDS_ROW) * 2;   // 147456
    const int SM64  = 2 * (2*TM*LDS_ROW + 2*64*LDS_ROW) * 2;    // 110592
    cudaFuncSetAttribute(mma_gemm<128>, cudaFuncAttributeMaxDynamicSharedMemorySize, SM128);
    cudaFuncSetAttribute(mma_gemm<64>,  cudaFuncAttributeMaxDynamicSharedMemorySize, SM64);

    const long long SSS = (long long)SS*SS;

    // 0) split weights
    split_kernel<<<3*EE*EE/4/256, 256>>>(w_in,   win_hi, win_lo, 3*EE*EE);
    split_kernel<<<EE*EE/4/256,   256>>>(w_out,  wout_hi, wout_lo, EE*EE);
    split_kernel<<<4*EE*EE/4/256, 256>>>(w_fc,   wfc_hi, wfc_lo, 4*EE*EE);
    split_kernel<<<4*EE*EE/4/256, 256>>>(w_proj, wpr_hi, wpr_lo, 4*EE*EE);

    // 1) LN1 -> split
    ln_split_kernel<<<ROWS, 256>>>(x, ln1_g, ln1_b, h_hi, h_lo);

    // 2) QKV = h @ w_in^T + b_in -> split
    mma_gemm<128><<<dim3(24, 32, 1), 256, SM128>>>(
        h_hi, h_lo, EE, 0, 0,
        win_hi, win_lo, EE, 0, 0,
        nullptr, qkv_hi, qkv_lo, 3*EE, 0, 0,
        b_in, nullptr, EE, 1, 1.f, FLAG_SPLIT);

    // 3) V transpose
    transpose_v<<<dim3(SS/32, DH/32, BB*HH), dim3(32,8)>>>(qkv_hi, qkv_lo, vt_hi, vt_lo);

    // 4) scores = 0.125 * q @ k^T -> split (fully-masked tiles skipped)
    mma_gemm<128><<<dim3(8, 8, BB*HH), 256, SM128>>>(
        qkv_hi, qkv_lo, 3*EE, (long long)SS*3*EE, DH,
        qkv_hi + EE, qkv_lo + EE, 3*EE, (long long)SS*3*EE, DH,
        nullptr, p_hi, p_lo, SS, (long long)HH*SSS, SSS,
        nullptr, nullptr, DH, HH, 0.125f, FLAG_CAUSAL | FLAG_SPLIT);

    // 5+6) fused softmax + att_weights
    softmax_attw<<<ROWS, 256>>>(p_hi, p_lo, out_w);

    // 7) att = P @ V^T (vt is [d, s] K-major), K clipped causally -> split
    mma_gemm<64><<<dim3(1, 8, BB*HH), 256, SM64>>>(
        p_hi, p_lo, SS, (long long)HH*SSS, SSS,
        vt_hi, vt_lo, SS, (long long)HH*DH*SS, (long long)DH*SS,
        nullptr, att_hi, att_lo, EE, (long long)SS*EE, DH,
        nullptr, nullptr, SS, HH, 1.f, FLAG_CLIPK | FLAG_SPLIT);

    // 8) x1 = x + att @ w_out^T + b_out (f32)
    mma_gemm<128><<<dim3(8, 32, 1), 256, SM128>>>(
        att_hi, att_lo, EE, 0, 0,
        wout_hi, wout_lo, EE, 0, 0,
        x1, nullptr, nullptr, EE, 0, 0,
        b_out, x, EE, 1, 1.f, 0);

    // 9) LN2 -> split
    ln_split_kernel<<<ROWS, 256>>>(x1, ln2_g, ln2_b, h2_hi, h2_lo);

    // 10) fc = gelu(h2 @ w_fc^T + b_fc) -> split
    mma_gemm<128><<<dim3(32, 32, 1), 256, SM128>>>(
        h2_hi, h2_lo, EE, 0, 0,
        wfc_hi, wfc_lo, EE, 0, 0,
        nullptr, fc_hi, fc_lo, 4*EE, 0, 0,
        b_fc, nullptr, EE, 1, 1.f, FLAG_SPLIT | FLAG_GELU);

    // 11) out_x = x1 + fc @ w_proj^T + b_proj (f32)
    mma_gemm<128><<<dim3(8, 32, 1), 256, SM128>>>(
        fc_hi, fc_lo, 4*EE, 0, 0,
        wpr_hi, wpr_lo, 4*EE, 0, 0,
        out_x, nullptr, nullptr, EE, 0, 0,
        b_proj, x1, 4*EE, 1, 1.f, 0);
}

// round 11
// speedup vs baseline: 1.5484x; 1.5484x over previous
#include <cuda_runtime.h>
#include <cuda_fp16.h>
#include <math.h>
#include <stdint.h>

#define BB 4
#define SS 1024
#define EE 1024
#define HH 16
#define DH 64
#define ROWS (BB*SS)
#define LN_EPS 1e-5f

typedef unsigned short u16;
typedef unsigned int   u32;
typedef unsigned long long u64;

#define LO_SCALE 2048.0f
#define LO_INV   (1.0f/2048.0f)

// ---------------- scratch (device globals; no allocation allowed) ----------------
__device__ u16 g_h_hi [ROWS*EE],    g_h_lo [ROWS*EE];
__device__ u16 g_qkv_hi[ROWS*3*EE], g_qkv_lo[ROWS*3*EE];
__device__ u16 g_vt_hi[BB*HH*DH*SS], g_vt_lo[BB*HH*DH*SS];
__device__ u16 g_p_hi[(long long)BB*HH*SS*SS], g_p_lo[(long long)BB*HH*SS*SS];
__device__ u16 g_att_hi[ROWS*EE],   g_att_lo[ROWS*EE];
__device__ float g_x1[ROWS*EE];
__device__ u16 g_h2_hi[ROWS*EE],    g_h2_lo[ROWS*EE];
__device__ u16 g_fc_hi[ROWS*4*EE],  g_fc_lo[ROWS*4*EE];
__device__ u16 g_win_hi [3*EE*EE],  g_win_lo [3*EE*EE];
__device__ u16 g_wout_hi[EE*EE],    g_wout_lo[EE*EE];
__device__ u16 g_wfc_hi [4*EE*EE],  g_wfc_lo [4*EE*EE];
__device__ u16 g_wpr_hi [4*EE*EE],  g_wpr_lo [4*EE*EE];

// ---------------- helpers (fp16 split: x = hi + lo/2048) ----------------
__device__ __forceinline__ float h2f(u16 u){ return __half2float(__ushort_as_half(u)); }
__device__ __forceinline__ u16 f2h(float f){ return __half_as_ushort(__float2half_rn(f)); }
__device__ __forceinline__ u32 smem_u32(const void* p){
    u32 a; asm("{ .reg .u64 t; cvta.to.shared.u64 t, %1; cvt.u32.u64 %0, t; }" : "=r"(a) : "l"(p));
    return a;
}
__device__ __forceinline__ void cp16(u32 dst, const void* src){
    asm volatile("cp.async.cg.shared.global [%0], [%1], 16;\n" :: "r"(dst), "l"(src));
}
#define CP_COMMIT() asm volatile("cp.async.commit_group;\n" ::: "memory")
#define CP_WAIT0()  asm volatile("cp.async.wait_group 0;\n" ::: "memory")
#define CP_WAIT1()  asm volatile("cp.async.wait_group 1;\n" ::: "memory")

__device__ __forceinline__ void ldmx4(u32& r0, u32& r1, u32& r2, u32& r3, u32 addr){
    asm volatile("ldmatrix.sync.aligned.m8n8.x4.shared.b16 {%0,%1,%2,%3}, [%4];"
        : "=r"(r0),"=r"(r1),"=r"(r2),"=r"(r3) : "r"(addr));
}
__device__ __forceinline__ void ldmx2(u32& r0, u32& r1, u32 addr){
    asm volatile("ldmatrix.sync.aligned.m8n8.x2.shared.b16 {%0,%1}, [%2];"
        : "=r"(r0),"=r"(r1) : "r"(addr));
}
// f32-accumulator fp16 HMMA (main product)
__device__ __forceinline__ void mma16816(float* c, const u32* a, const u32* b){
    asm volatile("mma.sync.aligned.m16n8k16.row.col.f32.f16.f16.f32 "
        "{%0,%1,%2,%3}, {%4,%5,%6,%7}, {%8,%9}, {%0,%1,%2,%3};"
        : "+f"(c[0]),"+f"(c[1]),"+f"(c[2]),"+f"(c[3])
        : "r"(a[0]),"r"(a[1]),"r"(a[2]),"r"(a[3]), "r"(b[0]),"r"(b[1]));
}
// f16-accumulator fp16 HMMA (correction products)
__device__ __forceinline__ void mma16816h(u32* c, const u32* a, const u32* b){
    asm volatile("mma.sync.aligned.m16n8k16.row.col.f16.f16.f16.f16 "
        "{%0,%1}, {%2,%3,%4,%5}, {%6,%7}, {%0,%1};"
        : "+r"(c[0]),"+r"(c[1])
        : "r"(a[0]),"r"(a[1]),"r"(a[2]),"r"(a[3]), "r"(b[0]),"r"(b[1]));
}

// flags
#define FLAG_GELU   1
#define FLAG_CAUSAL 2
#define FLAG_CLIPK  4
#define FLAG_SPLIT  8

#define TM 128
#define KT 64
#define LDS_ROW 72          // 64 k-elems + 8 pad (144B row stride; conflict-free ldmatrix)

// ---------------- HMMA fp16-split GEMM ----------------
// C = alpha * A·B^T (+bias/+resid/gelu/split).  A [M,K] K-major hi/lo; B [N,K] K-major hi/lo.
// hi·hi in f32 acc; corrections (lo pre-scaled x2048) in f16 acc, merged /2048.
// ASB=true: A is a single exact fp16 matrix (no lo) -> 2 products.
template<int TN, bool ASB>
__global__ __launch_bounds__(256, 1)
void mma_gemm(const u16* __restrict__ Ahi, const u16* __restrict__ Alo, int lda,
              long long sAb, long long sAh,
              const u16* __restrict__ Bhi, const u16* __restrict__ Blo, int ldb,
              long long sBb, long long sBh,
              float* __restrict__ Cf, u16* __restrict__ Chi, u16* __restrict__ Clo, int ldc,
              long long sCb, long long sCh,
              const float* __restrict__ bias, const float* __restrict__ resid,
              int K, int Hdiv, float alpha, int flags)
{
    constexpr int WM = 4;                        // warp grid m (32-row warp tiles: low regs)
    constexpr int WN = 2;                        // warp grid n
    constexpr int MT = TM / (WM * 16);           // 2 m16 tiles per warp
    constexpr int NT = TN / (WN * 8);            // n8 tiles per warp
    constexpr int OA = TM * LDS_ROW;             // elems per A buf
    constexpr int OB = TN * LDS_ROW;
    constexpr int STG = 2*OA + 2*OB;             // elems per stage (Ahi,Alo,Bhi,Blo)

    int m0 = blockIdx.y * TM;
    int n0 = blockIdx.x * TN;
    if ((flags & FLAG_CAUSAL) && n0 >= m0 + TM) return;   // fully masked tile

    int z  = blockIdx.z;
    int bb = z / Hdiv, hh = z % Hdiv;
    const u16* Ah = Ahi + bb*sAb + hh*sAh + (long long)m0*lda;
    const u16* Al = Alo + bb*sAb + hh*sAh + (long long)m0*lda;
    const u16* Bh = Bhi + bb*sBb + hh*sBh + (long long)n0*ldb;
    const u16* Bl = Blo + bb*sBb + hh*sBh + (long long)n0*ldb;

    int Keff = K;
    if (flags & FLAG_CLIPK) { int lim = m0 + TM; Keff = (lim < K) ? lim : K; }
    int T = Keff / KT;

    extern __shared__ __align__(128) u16 sm[];
    u32 sbase = smem_u32(sm);
    int tid = threadIdx.x;
    int lane = tid & 31, wid = tid >> 5;
    int warp_m = wid / WN, warp_n = wid % WN;

    auto load_tile = [&](int s, int k0){
        u32 base = sbase + s * STG * 2;
        for (int e = tid; e < TM*8; e += 256) {
            int r = e >> 3, c = e & 7;
            u32 off = (u32)(r*LDS_ROW*2 + c*16);
            long long g = (long long)r*lda + k0 + c*8;
            cp16(base + off, Ah + g);
            if (!ASB) cp16(base + OA*2 + off, Al + g);
        }
        for (int e = tid; e < TN*8; e += 256) {
            int r = e >> 3, c = e & 7;
            u32 off = (u32)(r*LDS_ROW*2 + c*16);
            long long g = (long long)r*ldb + k0 + c*8;
            cp16(base + 4*OA + off,         Bh + g);
            cp16(base + 4*OA + 2*OB + off,  Bl + g);
        }
    };

    float acc[MT][NT][4];
    u32  acch[MT][NT][2];
    #pragma unroll
    for (int i = 0; i < MT; i++)
        #pragma unroll
        for (int j = 0; j < NT; j++) {
            #pragma unroll
            for (int q = 0; q < 4; q++) acc[i][j][q] = 0.f;
            acch[i][j][0] = 0u; acch[i][j][1] = 0u;
        }

    load_tile(0, 0); CP_COMMIT();

    for (int t = 0; t < T; ++t) {
        if (t + 1 < T) { load_tile((t+1) & 1, (t+1)*KT); CP_COMMIT(); CP_WAIT1(); }
        else           { CP_WAIT0(); }
        __syncthreads();

        int s = t & 1;
        u32 aHiB = sbase + s*STG*2;
        u32 aLoB = aHiB + OA*2;
        u32 bHiB = aHiB + 4*OA;
        u32 bLoB = bHiB + OB*2;

        #pragma unroll
        for (int ks = 0; ks < 4; ks++) {
            u32 aHi[MT][4], aLo[MT][4], bHi[NT][2], bLo[NT][2];
            #pragma unroll
            for (int mt = 0; mt < MT; mt++) {
                int row = warp_m*MT*16 + mt*16 + (lane & 15);
                u32 off = (u32)(row*LDS_ROW*2 + ks*32 + (lane >> 4)*16);
                ldmx4(aHi[mt][0], aHi[mt][1], aHi[mt][2], aHi[mt][3], aHiB + off);
                if (!ASB) ldmx4(aLo[mt][0], aLo[mt][1], aLo[mt][2], aLo[mt][3], aLoB + off);
            }
            #pragma unroll
            for (int nt = 0; nt < NT; nt++) {
                int row = warp_n*NT*8 + nt*8 + (lane & 7);
                u32 off = (u32)(row*LDS_ROW*2 + ks*32 + ((lane >> 3) & 1)*16);
                ldmx2(bHi[nt][0], bHi[nt][1], bHiB + off);
                ldmx2(bLo[nt][0], bLo[nt][1], bLoB + off);
            }
            #pragma unroll
            for (int mt = 0; mt < MT; mt++)
                #pragma unroll
                for (int nt = 0; nt < NT; nt++) {
                    mma16816 (acc[mt][nt],  aHi[mt], bHi[nt]);   // main, f32 acc
                    mma16816h(acch[mt][nt], aHi[mt], bLo[nt]);   // corrections, f16 acc
                    if (!ASB) mma16816h(acch[mt][nt], aLo[mt], bHi[nt]);
                }
        }
        __syncthreads();
    }

    // ---- epilogue (packed stores: lanes own (n, n+1) pairs) ----
    long long cb = bb*sCb + hh*sCh;
    #pragma unroll
    for (int mt = 0; mt < MT; mt++) {
        #pragma unroll
        for (int nt = 0; nt < NT; nt++) {
            int rr = m0 + warp_m*MT*16 + mt*16 + (lane >> 2);
            int nn = n0 + warp_n*NT*8 + nt*8 + (lane & 3)*2;
            #pragma unroll
            for (int half = 0; half < 2; half++) {
                int m = rr + half*8;
                long long crow = cb + (long long)m*ldc;
                half2 hc = *reinterpret_cast<half2*>(&acch[mt][nt][half]);
                float corr[2] = { __low2float(hc), __high2float(hc) };
                float v[2];
                #pragma unroll
                for (int j = 0; j < 2; j++) {
                    float vv = (acc[mt][nt][half*2 + j] + corr[j]*LO_INV) * alpha;
                    int n = nn + j;
                    if (bias)  vv += bias[n];
                    if (resid) vv += resid[crow + n];
                    if (flags & FLAG_GELU) {
                        float tg = tanhf(0.7978845608028654f * (vv + 0.044715f*vv*vv*vv));
                        vv = 0.5f * vv * (1.f + tg);
                    }
                    v[j] = vv;
                }
                if (flags & FLAG_SPLIT) {
                    u16 h0 = f2h(v[0]), h1 = f2h(v[1]);
                    u16 l0 = f2h((v[0] - h2f(h0))*LO_SCALE), l1 = f2h((v[1] - h2f(h1))*LO_SCALE);
                    *reinterpret_cast<u32*>(Chi + crow + nn) = (u32)h0 | ((u32)h1 << 16);
                    *reinterpret_cast<u32*>(Clo + crow + nn) = (u32)l0 | ((u32)l1 << 16);
                } else {
                    *reinterpret_cast<float2*>(Cf + crow + nn) = make_float2(v[0], v[1]);
                }
            }
        }
    }
}

// ---------------- LayerNorm -> fp16 split ----------------
__global__ void ln_split_kernel(const float* __restrict__ x,
                                const float* __restrict__ g,
                                const float* __restrict__ b,
                                u16* __restrict__ ohi, u16* __restrict__ olo)
{
    long long row = blockIdx.x;
    const float* xr = x + row * EE;
    __shared__ float red[256];
    int tid = threadIdx.x;

    float s = 0.f;
    for (int c = tid; c < EE; c += 256) s += xr[c];
    red[tid] = s; __syncthreads();
    for (int st = 128; st > 0; st >>= 1){ if (tid < st) red[tid] += red[tid+st]; __syncthreads(); }
    float mu = red[0] * (1.f/EE); __syncthreads();

    float v = 0.f;
    for (int c = tid; c < EE; c += 256){ float d = xr[c]-mu; v += d*d; }
    red[tid] = v; __syncthreads();
    for (int st = 128; st > 0; st >>= 1){ if (tid < st) red[tid] += red[tid+st]; __syncthreads(); }
    float inv = rsqrtf(red[0]*(1.f/EE) + LN_EPS); __syncthreads();

    for (int c = tid; c < EE; c += 256) {
        float o = (xr[c]-mu)*inv*g[c] + b[c];
        u16 hi = f2h(o);
        ohi[row*EE + c] = hi;
        olo[row*EE + c] = f2h((o - h2f(hi))*LO_SCALE);
    }
}

// ---------------- split f32 -> fp16 hi/lo ----------------
__global__ void split_kernel(const float* __restrict__ src, u16* __restrict__ hi,
                             u16* __restrict__ lo, long long n)
{
    long long i = ((long long)blockIdx.x * 256 + threadIdx.x) * 4;
    if (i >= n) return;
    float4 v = *reinterpret_cast<const float4*>(src + i);
    float vv[4] = {v.x, v.y, v.z, v.w};
    u16 h[4], l[4];
    #pragma unroll
    for (int j = 0; j < 4; j++){ h[j] = f2h(vv[j]); l[j] = f2h((vv[j] - h2f(h[j]))*LO_SCALE); }
    *reinterpret_cast<u64*>(hi + i) = *(u64*)h;
    *reinterpret_cast<u64*>(lo + i) = *(u64*)l;
}

// ---------------- transpose V: qkv[b,s, 2E + h*64 + d] -> vt[(b,h), d, s] ----------------
__global__ void transpose_v(const u16* __restrict__ qh, const u16* __restrict__ ql,
                            u16* __restrict__ vth, u16* __restrict__ vtl)
{
    __shared__ u16 th[32][33], tl[32][33];
    int bh = blockIdx.z; int b = bh >> 4, h = bh & 15;
    int s0 = blockIdx.x * 32, d0 = blockIdx.y * 32;
    int tx = threadIdx.x, ty = threadIdx.y;
    #pragma unroll
    for (int i = 0; i < 4; i++) {
        int s = s0 + ty + i*8;
        long long src = ((long long)(b*SS + s))*(3*EE) + 2*EE + h*DH + d0 + tx;
        th[ty + i*8][tx] = qh[src];
        tl[ty + i*8][tx] = ql[src];
    }
    __syncthreads();
    #pragma unroll
    for (int i = 0; i < 4; i++) {
        int d = d0 + ty + i*8;
        long long dst = ((long long)(bh*DH + d))*SS + s0 + tx;
        vth[dst] = th[tx][ty + i*8];
        vtl[dst] = tl[tx][ty + i*8];
    }
}

// ---------------- fused causal softmax (all heads) + att_weights ----------------
// One block per (b, q). Probs written (single fp16) only to k < (q/128+1)*128.
__global__ void softmax_attw(u16* __restrict__ ph, const u16* __restrict__ pl,
                             float* __restrict__ outw)
{
    int bq = blockIdx.x;            // b*SS + q
    int b = bq >> 10, q = bq & (SS-1);
    int Lw = ((q >> 7) + 1) << 7;   // write length (multiple of 128)
    int tid = threadIdx.x;          // 256
    __shared__ float row[SS];
    __shared__ float red[256];
    float aw[4] = {0.f, 0.f, 0.f, 0.f};

    for (int h = 0; h < HH; h++) {
        long long base = (((long long)(b*HH + h)) << 20) | ((long long)q << 10);
        float mx = -1e30f;
        for (int c = tid; c <= q; c += 256) {
            float v = h2f(ph[base+c]) + h2f(pl[base+c])*LO_INV;
            row[c] = v;
            mx = fmaxf(mx, v);
        }
        red[tid] = mx; __syncthreads();
        for (int st = 128; st > 0; st >>= 1){ if (tid < st) red[tid] = fmaxf(red[tid], red[tid+st]); __syncthreads(); }
        mx = red[0]; __syncthreads();

        float sum = 0.f;
        for (int c = tid; c <= q; c += 256){ float e = __expf(row[c]-mx); row[c] = e; sum += e; }
        red[tid] = sum; __syncthreads();
        for (int st = 128; st > 0; st >>= 1){ if (tid < st) red[tid] += red[tid+st]; __syncthreads(); }
        float inv = 1.f / red[0]; __syncthreads();

        for (int c = tid; c < Lw; c += 256) {
            float p = (c <= q) ? row[c]*inv : 0.f;
            ph[base+c] = f2h(p);
            aw[c >> 8] += p;
        }
    }
    long long ob = ((long long)bq) << 10;
    #pragma unroll
    for (int i = 0; i < 4; i++) {
        int c = tid + 256*i;
        outw[ob + c] = (c <= q) ? aw[i]*(1.f/HH) : 0.f;
    }
}

// ---------------- launch ----------------
extern "C" void kernel_launch(void* const* d_in, const int* in_sizes, int n_in,
                              void* d_out, int out_size)
{
    const float* x      = (const float*)d_in[0];
    const float* ln1_g  = (const float*)d_in[2];
    const float* ln1_b  = (const float*)d_in[3];
    const float* ln2_g  = (const float*)d_in[4];
    const float* ln2_b  = (const float*)d_in[5];
    const float* w_in   = (const float*)d_in[6];
    const float* b_in   = (const float*)d_in[7];
    const float* w_out  = (const float*)d_in[8];
    const float* b_out  = (const float*)d_in[9];
    const float* w_fc   = (const float*)d_in[10];
    const float* b_fc   = (const float*)d_in[11];
    const float* w_proj = (const float*)d_in[12];
    const float* b_proj = (const float*)d_in[13];

    float* out_x = (float*)d_out;
    float* out_w = (float*)d_out + (long long)ROWS*EE;

    u16 *h_hi,*h_lo,*qkv_hi,*qkv_lo,*vt_hi,*vt_lo,*p_hi,*p_lo,*att_hi,*att_lo,*h2_hi,*h2_lo,*fc_hi,*fc_lo;
    u16 *win_hi,*win_lo,*wout_hi,*wout_lo,*wfc_hi,*wfc_lo,*wpr_hi,*wpr_lo;
    float *x1;
    cudaGetSymbolAddress((void**)&h_hi, g_h_hi);     cudaGetSymbolAddress((void**)&h_lo, g_h_lo);
    cudaGetSymbolAddress((void**)&qkv_hi, g_qkv_hi); cudaGetSymbolAddress((void**)&qkv_lo, g_qkv_lo);
    cudaGetSymbolAddress((void**)&vt_hi, g_vt_hi);   cudaGetSymbolAddress((void**)&vt_lo, g_vt_lo);
    cudaGetSymbolAddress((void**)&p_hi, g_p_hi);     cudaGetSymbolAddress((void**)&p_lo, g_p_lo);
    cudaGetSymbolAddress((void**)&att_hi, g_att_hi); cudaGetSymbolAddress((void**)&att_lo, g_att_lo);
    cudaGetSymbolAddress((void**)&x1, g_x1);
    cudaGetSymbolAddress((void**)&h2_hi, g_h2_hi);   cudaGetSymbolAddress((void**)&h2_lo, g_h2_lo);
    cudaGetSymbolAddress((void**)&fc_hi, g_fc_hi);   cudaGetSymbolAddress((void**)&fc_lo, g_fc_lo);
    cudaGetSymbolAddress((void**)&win_hi, g_win_hi); cudaGetSymbolAddress((void**)&win_lo, g_win_lo);
    cudaGetSymbolAddress((void**)&wout_hi, g_wout_hi); cudaGetSymbolAddress((void**)&wout_lo, g_wout_lo);
    cudaGetSymbolAddress((void**)&wfc_hi, g_wfc_hi); cudaGetSymbolAddress((void**)&wfc_lo, g_wfc_lo);
    cudaGetSymbolAddress((void**)&wpr_hi, g_wpr_hi); cudaGetSymbolAddress((void**)&wpr_lo, g_wpr_lo);

    const int SM128 = 2 * (2*TM*LDS_ROW + 2*128*LDS_ROW) * 2;   // 147456
    const int SM64  = 2 * (2*TM*LDS_ROW + 2*64*LDS_ROW) * 2;    // 110592
    cudaFuncSetAttribute((const void*)mma_gemm<128,false>, cudaFuncAttributeMaxDynamicSharedMemorySize, SM128);
    cudaFuncSetAttribute((const void*)mma_gemm<64,true>,   cudaFuncAttributeMaxDynamicSharedMemorySize, SM64);

    const long long SSS = (long long)SS*SS;

    // 0) split weights
    split_kernel<<<3*EE*EE/4/256, 256>>>(w_in,   win_hi, win_lo, 3*EE*EE);
    split_kernel<<<EE*EE/4/256,   256>>>(w_out,  wout_hi, wout_lo, EE*EE);
    split_kernel<<<4*EE*EE/4/256, 256>>>(w_fc,   wfc_hi, wfc_lo, 4*EE*EE);
    split_kernel<<<4*EE*EE/4/256, 256>>>(w_proj, wpr_hi, wpr_lo, 4*EE*EE);

    // 1) LN1 -> split
    ln_split_kernel<<<ROWS, 256>>>(x, ln1_g, ln1_b, h_hi, h_lo);

    // 2) QKV = h @ w_in^T + b_in -> split
    mma_gemm<128,false><<<dim3(24, 32, 1), 256, SM128>>>(
        h_hi, h_lo, EE, 0, 0,
        win_hi, win_lo, EE, 0, 0,
        nullptr, qkv_hi, qkv_lo, 3*EE, 0, 0,
        b_in, nullptr, EE, 1, 1.f, FLAG_SPLIT);

    // 3) V transpose
    transpose_v<<<dim3(SS/32, DH/32, BB*HH), dim3(32,8)>>>(qkv_hi, qkv_lo, vt_hi, vt_lo);

    // 4) scores = 0.125 * q @ k^T -> split (fully-masked tiles skipped)
    mma_gemm<128,false><<<dim3(8, 8, BB*HH), 256, SM128>>>(
        qkv_hi, qkv_lo, 3*EE, (long long)SS*3*EE, DH,
        qkv_hi + EE, qkv_lo + EE, 3*EE, (long long)SS*3*EE, DH,
        nullptr, p_hi, p_lo, SS, (long long)HH*SSS, SSS,
        nullptr, nullptr, DH, HH, 0.125f, FLAG_CAUSAL | FLAG_SPLIT);

    // 5+6) fused softmax + att_weights (probs -> single fp16 in p_hi)
    softmax_attw<<<ROWS, 256>>>(p_hi, p_lo, out_w);

    // 7) att = P @ V^T (A single fp16; vt split, K clipped causally) -> split
    mma_gemm<64,true><<<dim3(1, 8, BB*HH), 256, SM64>>>(
        p_hi, p_hi, SS, (long long)HH*SSS, SSS,
        vt_hi, vt_lo, SS, (long long)HH*DH*SS, (long long)DH*SS,
        nullptr, att_hi, att_lo, EE, (long long)SS*EE, DH,
        nullptr, nullptr, SS, HH, 1.f, FLAG_CLIPK | FLAG_SPLIT);

    // 8) x1 = x + att @ w_out^T + b_out (f32)
    mma_gemm<128,false><<<dim3(8, 32, 1), 256, SM128>>>(
        att_hi, att_lo, EE, 0, 0,
        wout_hi, wout_lo, EE, 0, 0,
        x1, nullptr, nullptr, EE, 0, 0,
        b_out, x, EE, 1, 1.f, 0);

    // 9) LN2 -> split
    ln_split_kernel<<<ROWS, 256>>>(x1, ln2_g, ln2_b, h2_hi, h2_lo);

    // 10) fc = gelu(h2 @ w_fc^T + b_fc) -> split
    mma_gemm<128,false><<<dim3(32, 32, 1), 256, SM128>>>(
        h2_hi, h2_lo, EE, 0, 0,
        wfc_hi, wfc_lo, EE, 0, 0,
        nullptr, fc_hi, fc_lo, 4*EE, 0, 0,
        b_fc, nullptr, EE, 1, 1.f, FLAG_SPLIT | FLAG_GELU);

    // 11) out_x = x1 + fc @ w_proj^T + b_proj (f32)
    mma_gemm<128,false><<<dim3(8, 32, 1), 256, SM128>>>(
        fc_hi, fc_lo, 4*EE, 0, 0,
        wpr_hi, wpr_lo, 4*EE, 0, 0,
        out_x, nullptr, nullptr, EE, 0, 0,
        b_proj, x1, 4*EE, 1, 1.f, 0);
}

// round 12
// speedup vs baseline: 1.8826x; 1.2158x over previous
#include <cuda_runtime.h>
#include <cuda_fp16.h>
#include <math.h>
#include <stdint.h>

#define BB 4
#define SS 1024
#define EE 1024
#define HH 16
#define DH 64
#define ROWS (BB*SS)
#define LN_EPS 1e-5f

typedef unsigned short u16;
typedef unsigned int   u32;
typedef unsigned long long u64;

#define LO_SCALE 2048.0f
#define LO_INV   (1.0f/2048.0f)

// ---------------- scratch (device globals; no allocation allowed) ----------------
__device__ u16 g_h_hi [ROWS*EE],    g_h_lo [ROWS*EE];
__device__ u16 g_qkv_hi[ROWS*3*EE], g_qkv_lo[ROWS*3*EE];
__device__ u16 g_vt_hi[BB*HH*DH*SS], g_vt_lo[BB*HH*DH*SS];
__device__ u16 g_p_hi[(long long)BB*HH*SS*SS], g_p_lo[(long long)BB*HH*SS*SS];
__device__ u16 g_att_hi[ROWS*EE],   g_att_lo[ROWS*EE];
__device__ float g_x1[ROWS*EE];
__device__ u16 g_h2_hi[ROWS*EE],    g_h2_lo[ROWS*EE];
__device__ u16 g_fc_hi[ROWS*4*EE],  g_fc_lo[ROWS*4*EE];
__device__ u16 g_win_h [3*EE*EE];
__device__ u16 g_wout_h[EE*EE];
__device__ u16 g_wfc_h [4*EE*EE];
__device__ u16 g_wpr_h [4*EE*EE];

// ---------------- helpers (fp16 split: x = hi + lo/2048) ----------------
__device__ __forceinline__ float h2f(u16 u){ return __half2float(__ushort_as_half(u)); }
__device__ __forceinline__ u16 f2h(float f){ return __half_as_ushort(__float2half_rn(f)); }
__device__ __forceinline__ u32 smem_u32(const void* p){
    u32 a; asm("{ .reg .u64 t; cvta.to.shared.u64 t, %1; cvt.u32.u64 %0, t; }" : "=r"(a) : "l"(p));
    return a;
}
__device__ __forceinline__ void cp16(u32 dst, const void* src){
    asm volatile("cp.async.cg.shared.global [%0], [%1], 16;\n" :: "r"(dst), "l"(src));
}
#define CP_COMMIT() asm volatile("cp.async.commit_group;\n" ::: "memory")
#define CP_WAIT0()  asm volatile("cp.async.wait_group 0;\n" ::: "memory")
#define CP_WAIT1()  asm volatile("cp.async.wait_group 1;\n" ::: "memory")

__device__ __forceinline__ void ldmx4(u32& r0, u32& r1, u32& r2, u32& r3, u32 addr){
    asm volatile("ldmatrix.sync.aligned.m8n8.x4.shared.b16 {%0,%1,%2,%3}, [%4];"
        : "=r"(r0),"=r"(r1),"=r"(r2),"=r"(r3) : "r"(addr));
}
__device__ __forceinline__ void ldmx2(u32& r0, u32& r1, u32 addr){
    asm volatile("ldmatrix.sync.aligned.m8n8.x2.shared.b16 {%0,%1}, [%2];"
        : "=r"(r0),"=r"(r1) : "r"(addr));
}
// f32-accumulator fp16 HMMA (main product)
__device__ __forceinline__ void mma16816(float* c, const u32* a, const u32* b){
    asm volatile("mma.sync.aligned.m16n8k16.row.col.f32.f16.f16.f32 "
        "{%0,%1,%2,%3}, {%4,%5,%6,%7}, {%8,%9}, {%0,%1,%2,%3};"
        : "+f"(c[0]),"+f"(c[1]),"+f"(c[2]),"+f"(c[3])
        : "r"(a[0]),"r"(a[1]),"r"(a[2]),"r"(a[3]), "r"(b[0]),"r"(b[1]));
}
// f16-accumulator fp16 HMMA (correction products)
__device__ __forceinline__ void mma16816h(u32* c, const u32* a, const u32* b){
    asm volatile("mma.sync.aligned.m16n8k16.row.col.f16.f16.f16.f16 "
        "{%0,%1}, {%2,%3,%4,%5}, {%6,%7}, {%0,%1};"
        : "+r"(c[0]),"+r"(c[1])
        : "r"(a[0]),"r"(a[1]),"r"(a[2]),"r"(a[3]), "r"(b[0]),"r"(b[1]));
}

// flags
#define FLAG_GELU   1
#define FLAG_CAUSAL 2
#define FLAG_CLIPK  4
#define FLAG_SPLIT  8

// MODE: 0 = A split + B split (3 MMAs); 1 = A single + B split (2); 2 = A split + B single (2)
#define TM 128
#define KT 64
#define LDS_ROW 72          // 64 k-elems + 8 pad (144B row stride; conflict-free ldmatrix)

// ---------------- HMMA fp16-split GEMM ----------------
template<int TN, int MODE>
__global__ __launch_bounds__(256, 1)
void mma_gemm(const u16* __restrict__ Ahi, const u16* __restrict__ Alo, int lda,
              long long sAb, long long sAh,
              const u16* __restrict__ Bhi, const u16* __restrict__ Blo, int ldb,
              long long sBb, long long sBh,
              float* __restrict__ Cf, u16* __restrict__ Chi, u16* __restrict__ Clo, int ldc,
              long long sCb, long long sCh,
              const float* __restrict__ bias, const float* __restrict__ resid,
              int K, int Hdiv, float alpha, int flags)
{
    constexpr int WM = 4;                        // warp grid m (32-row warp tiles: low regs)
    constexpr int WN = 2;                        // warp grid n
    constexpr int MT = TM / (WM * 16);           // 2 m16 tiles per warp
    constexpr int NT = TN / (WN * 8);            // n8 tiles per warp
    constexpr int OA = TM * LDS_ROW;             // elems per A buf
    constexpr int OB = TN * LDS_ROW;
    constexpr int STG = 2*OA + 2*OB;             // elems per stage (layout fixed across modes)

    int m0 = blockIdx.y * TM;
    int n0 = blockIdx.x * TN;
    if ((flags & FLAG_CAUSAL) && n0 >= m0 + TM) return;   // fully masked tile

    int z  = blockIdx.z;
    int bb = z / Hdiv, hh = z % Hdiv;
    const u16* Ah = Ahi + bb*sAb + hh*sAh + (long long)m0*lda;
    const u16* Al = Alo + bb*sAb + hh*sAh + (long long)m0*lda;
    const u16* Bh = Bhi + bb*sBb + hh*sBh + (long long)n0*ldb;
    const u16* Bl = Blo + bb*sBb + hh*sBh + (long long)n0*ldb;

    int Keff = K;
    if (flags & FLAG_CLIPK) { int lim = m0 + TM; Keff = (lim < K) ? lim : K; }
    int T = Keff / KT;

    extern __shared__ __align__(128) u16 sm[];
    u32 sbase = smem_u32(sm);
    int tid = threadIdx.x;
    int lane = tid & 31, wid = tid >> 5;
    int warp_m = wid / WN, warp_n = wid % WN;

    auto load_tile = [&](int s, int k0){
        u32 base = sbase + s * STG * 2;
        for (int e = tid; e < TM*8; e += 256) {
            int r = e >> 3, c = e & 7;
            u32 off = (u32)(r*LDS_ROW*2 + c*16);
            long long g = (long long)r*lda + k0 + c*8;
            cp16(base + off, Ah + g);
            if (MODE != 1) cp16(base + OA*2 + off, Al + g);
        }
        for (int e = tid; e < TN*8; e += 256) {
            int r = e >> 3, c = e & 7;
            u32 off = (u32)(r*LDS_ROW*2 + c*16);
            long long g = (long long)r*ldb + k0 + c*8;
            cp16(base + 4*OA + off, Bh + g);
            if (MODE != 2) cp16(base + 4*OA + 2*OB + off, Bl + g);
        }
    };

    float acc[MT][NT][4];
    u32  acch[MT][NT][2];
    #pragma unroll
    for (int i = 0; i < MT; i++)
        #pragma unroll
        for (int j = 0; j < NT; j++) {
            #pragma unroll
            for (int q = 0; q < 4; q++) acc[i][j][q] = 0.f;
            acch[i][j][0] = 0u; acch[i][j][1] = 0u;
        }

    load_tile(0, 0); CP_COMMIT();

    for (int t = 0; t < T; ++t) {
        if (t + 1 < T) { load_tile((t+1) & 1, (t+1)*KT); CP_COMMIT(); CP_WAIT1(); }
        else           { CP_WAIT0(); }
        __syncthreads();

        int s = t & 1;
        u32 aHiB = sbase + s*STG*2;
        u32 aLoB = aHiB + OA*2;
        u32 bHiB = aHiB + 4*OA;
        u32 bLoB = bHiB + OB*2;

        #pragma unroll
        for (int ks = 0; ks < 4; ks++) {
            u32 aHi[MT][4], aLo[MT][4], bHi[NT][2], bLo[NT][2];
            #pragma unroll
            for (int mt = 0; mt < MT; mt++) {
                int row = warp_m*MT*16 + mt*16 + (lane & 15);
                u32 off = (u32)(row*LDS_ROW*2 + ks*32 + (lane >> 4)*16);
                ldmx4(aHi[mt][0], aHi[mt][1], aHi[mt][2], aHi[mt][3], aHiB + off);
                if (MODE != 1) ldmx4(aLo[mt][0], aLo[mt][1], aLo[mt][2], aLo[mt][3], aLoB + off);
            }
            #pragma unroll
            for (int nt = 0; nt < NT; nt++) {
                int row = warp_n*NT*8 + nt*8 + (lane & 7);
                u32 off = (u32)(row*LDS_ROW*2 + ks*32 + ((lane >> 3) & 1)*16);
                ldmx2(bHi[nt][0], bHi[nt][1], bHiB + off);
                if (MODE != 2) ldmx2(bLo[nt][0], bLo[nt][1], bLoB + off);
            }
            #pragma unroll
            for (int mt = 0; mt < MT; mt++)
                #pragma unroll
                for (int nt = 0; nt < NT; nt++) {
                    mma16816(acc[mt][nt], aHi[mt], bHi[nt]);                 // main, f32 acc
                    if (MODE != 2) mma16816h(acch[mt][nt], aHi[mt], bLo[nt]); // A·B_lo
                    if (MODE != 1) mma16816h(acch[mt][nt], aLo[mt], bHi[nt]); // A_lo·B
                }
        }
        __syncthreads();
    }

    // ---- epilogue (packed stores: lanes own (n, n+1) pairs) ----
    long long cb = bb*sCb + hh*sCh;
    #pragma unroll
    for (int mt = 0; mt < MT; mt++) {
        #pragma unroll
        for (int nt = 0; nt < NT; nt++) {
            int rr = m0 + warp_m*MT*16 + mt*16 + (lane >> 2);
            int nn = n0 + warp_n*NT*8 + nt*8 + (lane & 3)*2;
            #pragma unroll
            for (int half = 0; half < 2; half++) {
                int m = rr + half*8;
                long long crow = cb + (long long)m*ldc;
                half2 hc = *reinterpret_cast<half2*>(&acch[mt][nt][half]);
                float corr[2] = { __low2float(hc), __high2float(hc) };
                float v[2];
                #pragma unroll
                for (int j = 0; j < 2; j++) {
                    float vv = (acc[mt][nt][half*2 + j] + corr[j]*LO_INV) * alpha;
                    int n = nn + j;
                    if (bias)  vv += bias[n];
                    if (resid) vv += resid[crow + n];
                    if (flags & FLAG_GELU) {
                        float tg = tanhf(0.7978845608028654f * (vv + 0.044715f*vv*vv*vv));
                        vv = 0.5f * vv * (1.f + tg);
                    }
                    v[j] = vv;
                }
                if (flags & FLAG_SPLIT) {
                    u16 h0 = f2h(v[0]), h1 = f2h(v[1]);
                    u16 l0 = f2h((v[0] - h2f(h0))*LO_SCALE), l1 = f2h((v[1] - h2f(h1))*LO_SCALE);
                    *reinterpret_cast<u32*>(Chi + crow + nn) = (u32)h0 | ((u32)h1 << 16);
                    *reinterpret_cast<u32*>(Clo + crow + nn) = (u32)l0 | ((u32)l1 << 16);
                } else {
                    *reinterpret_cast<float2*>(Cf + crow + nn) = make_float2(v[0], v[1]);
                }
            }
        }
    }
}

// ---------------- LayerNorm -> fp16 split ----------------
__global__ void ln_split_kernel(const float* __restrict__ x,
                                const float* __restrict__ g,
                                const float* __restrict__ b,
                                u16* __restrict__ ohi, u16* __restrict__ olo)
{
    long long row = blockIdx.x;
    const float* xr = x + row * EE;
    __shared__ float red[256];
    int tid = threadIdx.x;

    float s = 0.f;
    for (int c = tid; c < EE; c += 256) s += xr[c];
    red[tid] = s; __syncthreads();
    for (int st = 128; st > 0; st >>= 1){ if (tid < st) red[tid] += red[tid+st]; __syncthreads(); }
    float mu = red[0] * (1.f/EE); __syncthreads();

    float v = 0.f;
    for (int c = tid; c < EE; c += 256){ float d = xr[c]-mu; v += d*d; }
    red[tid] = v; __syncthreads();
    for (int st = 128; st > 0; st >>= 1){ if (tid < st) red[tid] += red[tid+st]; __syncthreads(); }
    float inv = rsqrtf(red[0]*(1.f/EE) + LN_EPS); __syncthreads();

    for (int c = tid; c < EE; c += 256) {
        float o = (xr[c]-mu)*inv*g[c] + b[c];
        u16 hi = f2h(o);
        ohi[row*EE + c] = hi;
        olo[row*EE + c] = f2h((o - h2f(hi))*LO_SCALE);
    }
}

// ---------------- convert f32 -> fp16 (weights; single plane) ----------------
__global__ void cvt_kernel(const float* __restrict__ src, u16* __restrict__ dst, long long n)
{
    long long i = ((long long)blockIdx.x * 256 + threadIdx.x) * 4;
    if (i >= n) return;
    float4 v = *reinterpret_cast<const float4*>(src + i);
    u16 h[4] = { f2h(v.x), f2h(v.y), f2h(v.z), f2h(v.w) };
    *reinterpret_cast<u64*>(dst + i) = *(u64*)h;
}

// ---------------- transpose V: qkv[b,s, 2E + h*64 + d] -> vt[(b,h), d, s] ----------------
__global__ void transpose_v(const u16* __restrict__ qh, const u16* __restrict__ ql,
                            u16* __restrict__ vth, u16* __restrict__ vtl)
{
    __shared__ u16 th[32][33], tl[32][33];
    int bh = blockIdx.z; int b = bh >> 4, h = bh & 15;
    int s0 = blockIdx.x * 32, d0 = blockIdx.y * 32;
    int tx = threadIdx.x, ty = threadIdx.y;
    #pragma unroll
    for (int i = 0; i < 4; i++) {
        int s = s0 + ty + i*8;
        long long src = ((long long)(b*SS + s))*(3*EE) + 2*EE + h*DH + d0 + tx;
        th[ty + i*8][tx] = qh[src];
        tl[ty + i*8][tx] = ql[src];
    }
    __syncthreads();
    #pragma unroll
    for (int i = 0; i < 4; i++) {
        int d = d0 + ty + i*8;
        long long dst = ((long long)(bh*DH + d))*SS + s0 + tx;
        vth[dst] = th[tx][ty + i*8];
        vtl[dst] = tl[tx][ty + i*8];
    }
}

// ---------------- fused causal softmax (all heads) + att_weights ----------------
// One block per (b, q). Probs written (single fp16) only to k < (q/128+1)*128.
__global__ void softmax_attw(u16* __restrict__ ph, const u16* __restrict__ pl,
                             float* __restrict__ outw)
{
    int bq = blockIdx.x;            // b*SS + q
    int b = bq >> 10, q = bq & (SS-1);
    int Lw = ((q >> 7) + 1) << 7;   // write length (multiple of 128)
    int tid = threadIdx.x;          // 256
    __shared__ float row[SS];
    __shared__ float red[256];
    float aw[4] = {0.f, 0.f, 0.f, 0.f};

    for (int h = 0; h < HH; h++) {
        long long base = (((long long)(b*HH + h)) << 20) | ((long long)q << 10);
        float mx = -1e30f;
        for (int c = tid; c <= q; c += 256) {
            float v = h2f(ph[base+c]) + h2f(pl[base+c])*LO_INV;
            row[c] = v;
            mx = fmaxf(mx, v);
        }
        red[tid] = mx; __syncthreads();
        for (int st = 128; st > 0; st >>= 1){ if (tid < st) red[tid] = fmaxf(red[tid], red[tid+st]); __syncthreads(); }
        mx = red[0]; __syncthreads();

        float sum = 0.f;
        for (int c = tid; c <= q; c += 256){ float e = __expf(row[c]-mx); row[c] = e; sum += e; }
        red[tid] = sum; __syncthreads();
        for (int st = 128; st > 0; st >>= 1){ if (tid < st) red[tid] += red[tid+st]; __syncthreads(); }
        float inv = 1.f / red[0]; __syncthreads();

        for (int c = tid; c < Lw; c += 256) {
            float p = (c <= q) ? row[c]*inv : 0.f;
            ph[base+c] = f2h(p);
            aw[c >> 8] += p;
        }
    }
    long long ob = ((long long)bq) << 10;
    #pragma unroll
    for (int i = 0; i < 4; i++) {
        int c = tid + 256*i;
        outw[ob + c] = (c <= q) ? aw[i]*(1.f/HH) : 0.f;
    }
}

// ---------------- launch ----------------
extern "C" void kernel_launch(void* const* d_in, const int* in_sizes, int n_in,
                              void* d_out, int out_size)
{
    const float* x      = (const float*)d_in[0];
    const float* ln1_g  = (const float*)d_in[2];
    const float* ln1_b  = (const float*)d_in[3];
    const float* ln2_g  = (const float*)d_in[4];
    const float* ln2_b  = (const float*)d_in[5];
    const float* w_in   = (const float*)d_in[6];
    const float* b_in   = (const float*)d_in[7];
    const float* w_out  = (const float*)d_in[8];
    const float* b_out  = (const float*)d_in[9];
    const float* w_fc   = (const float*)d_in[10];
    const float* b_fc   = (const float*)d_in[11];
    const float* w_proj = (const float*)d_in[12];
    const float* b_proj = (const float*)d_in[13];

    float* out_x = (float*)d_out;
    float* out_w = (float*)d_out + (long long)ROWS*EE;

    u16 *h_hi,*h_lo,*qkv_hi,*qkv_lo,*vt_hi,*vt_lo,*p_hi,*p_lo,*att_hi,*att_lo,*h2_hi,*h2_lo,*fc_hi,*fc_lo;
    u16 *win_h,*wout_h,*wfc_h,*wpr_h;
    float *x1;
    cudaGetSymbolAddress((void**)&h_hi, g_h_hi);     cudaGetSymbolAddress((void**)&h_lo, g_h_lo);
    cudaGetSymbolAddress((void**)&qkv_hi, g_qkv_hi); cudaGetSymbolAddress((void**)&qkv_lo, g_qkv_lo);
    cudaGetSymbolAddress((void**)&vt_hi, g_vt_hi);   cudaGetSymbolAddress((void**)&vt_lo, g_vt_lo);
    cudaGetSymbolAddress((void**)&p_hi, g_p_hi);     cudaGetSymbolAddress((void**)&p_lo, g_p_lo);
    cudaGetSymbolAddress((void**)&att_hi, g_att_hi); cudaGetSymbolAddress((void**)&att_lo, g_att_lo);
    cudaGetSymbolAddress((void**)&x1, g_x1);
    cudaGetSymbolAddress((void**)&h2_hi, g_h2_hi);   cudaGetSymbolAddress((void**)&h2_lo, g_h2_lo);
    cudaGetSymbolAddress((void**)&fc_hi, g_fc_hi);   cudaGetSymbolAddress((void**)&fc_lo, g_fc_lo);
    cudaGetSymbolAddress((void**)&win_h, g_win_h);
    cudaGetSymbolAddress((void**)&wout_h, g_wout_h);
    cudaGetSymbolAddress((void**)&wfc_h, g_wfc_h);
    cudaGetSymbolAddress((void**)&wpr_h, g_wpr_h);

    const int SM128 = 2 * (2*TM*LDS_ROW + 2*128*LDS_ROW) * 2;   // 147456
    const int SM64  = 2 * (2*TM*LDS_ROW + 2*64*LDS_ROW) * 2;    // 110592
    cudaFuncSetAttribute((const void*)mma_gemm<128,0>, cudaFuncAttributeMaxDynamicSharedMemorySize, SM128);
    cudaFuncSetAttribute((const void*)mma_gemm<128,2>, cudaFuncAttributeMaxDynamicSharedMemorySize, SM128);
    cudaFuncSetAttribute((const void*)mma_gemm<64,1>,  cudaFuncAttributeMaxDynamicSharedMemorySize, SM64);

    const long long SSS = (long long)SS*SS;

    // 0) convert weights -> single fp16
    cvt_kernel<<<3*EE*EE/4/256, 256>>>(w_in,   win_h, 3*EE*EE);
    cvt_kernel<<<EE*EE/4/256,   256>>>(w_out,  wout_h, EE*EE);
    cvt_kernel<<<4*EE*EE/4/256, 256>>>(w_fc,   wfc_h, 4*EE*EE);
    cvt_kernel<<<4*EE*EE/4/256, 256>>>(w_proj, wpr_h, 4*EE*EE);

    // 1) LN1 -> split
    ln_split_kernel<<<ROWS, 256>>>(x, ln1_g, ln1_b, h_hi, h_lo);

    // 2) QKV = h @ w_in^T + b_in (A split, B single) -> split
    mma_gemm<128,2><<<dim3(24, 32, 1), 256, SM128>>>(
        h_hi, h_lo, EE, 0, 0,
        win_h, win_h, EE, 0, 0,
        nullptr, qkv_hi, qkv_lo, 3*EE, 0, 0,
        b_in, nullptr, EE, 1, 1.f, FLAG_SPLIT);

    // 3) V transpose
    transpose_v<<<dim3(SS/32, DH/32, BB*HH), dim3(32,8)>>>(qkv_hi, qkv_lo, vt_hi, vt_lo);

    // 4) scores = 0.125 * q @ k^T (both split, 3 MMAs; masked tiles skipped) -> split
    mma_gemm<128,0><<<dim3(8, 8, BB*HH), 256, SM128>>>(
        qkv_hi, qkv_lo, 3*EE, (long long)SS*3*EE, DH,
        qkv_hi + EE, qkv_lo + EE, 3*EE, (long long)SS*3*EE, DH,
        nullptr, p_hi, p_lo, SS, (long long)HH*SSS, SSS,
        nullptr, nullptr, DH, HH, 0.125f, FLAG_CAUSAL | FLAG_SPLIT);

    // 5+6) fused softmax + att_weights (probs -> single fp16 in p_hi)
    softmax_attw<<<ROWS, 256>>>(p_hi, p_lo, out_w);

    // 7) att = P @ V^T (A single, B split; K clipped causally) -> split
    mma_gemm<64,1><<<dim3(1, 8, BB*HH), 256, SM64>>>(
        p_hi, p_hi, SS, (long long)HH*SSS, SSS,
        vt_hi, vt_lo, SS, (long long)HH*DH*SS, (long long)DH*SS,
        nullptr, att_hi, att_lo, EE, (long long)SS*EE, DH,
        nullptr, nullptr, SS, HH, 1.f, FLAG_CLIPK | FLAG_SPLIT);

    // 8) x1 = x + att @ w_out^T + b_out (A split, B single; f32 out)
    mma_gemm<128,2><<<dim3(8, 32, 1), 256, SM128>>>(
        att_hi, att_lo, EE, 0, 0,
        wout_h, wout_h, EE, 0, 0,
        x1, nullptr, nullptr, EE, 0, 0,
        b_out, x, EE, 1, 1.f, 0);

    // 9) LN2 -> split
    ln_split_kernel<<<ROWS, 256>>>(x1, ln2_g, ln2_b, h2_hi, h2_lo);

    // 10) fc = gelu(h2 @ w_fc^T + b_fc) (A split, B single) -> split
    mma_gemm<128,2><<<dim3(32, 32, 1), 256, SM128>>>(
        h2_hi, h2_lo, EE, 0, 0,
        wfc_h, wfc_h, EE, 0, 0,
        nullptr, fc_hi, fc_lo, 4*EE, 0, 0,
        b_fc, nullptr, EE, 1, 1.f, FLAG_SPLIT | FLAG_GELU);

    // 11) out_x = x1 + fc @ w_proj^T + b_proj (A split, B single; f32 out)
    mma_gemm<128,2><<<dim3(8, 32, 1), 256, SM128>>>(
        fc_hi, fc_lo, 4*EE, 0, 0,
        wpr_h, wpr_h, 4*EE, 0, 0,
        out_x, nullptr, nullptr, EE, 0, 0,
        b_proj, x1, 4*EE, 1, 1.f, 0);
}

// round 13
// speedup vs baseline: 2.4625x; 1.3080x over previous
#include <cuda_runtime.h>
#include <cuda_fp16.h>
#include <math.h>
#include <stdint.h>

#define BB 4
#define SS 1024
#define EE 1024
#define HH 16
#define DH 64
#define ROWS (BB*SS)
#define LN_EPS 1e-5f

typedef unsigned short u16;
typedef unsigned int   u32;
typedef unsigned long long u64;

#define LO_SCALE 2048.0f
#define LO_INV   (1.0f/2048.0f)

// ---------------- scratch (device globals; no allocation allowed) ----------------
__device__ u16 g_h_hi [ROWS*EE];
__device__ u16 g_qkv_hi[ROWS*3*EE], g_qkv_lo[ROWS*3*EE];
__device__ u16 g_vt_hi[BB*HH*DH*SS];
__device__ u16 g_p_hi[(long long)BB*HH*SS*SS], g_p_lo[(long long)BB*HH*SS*SS];
__device__ u16 g_att_hi[ROWS*EE];
__device__ float g_x1[ROWS*EE];
__device__ u16 g_h2_hi[ROWS*EE];
__device__ u16 g_fc_hi[ROWS*4*EE];
__device__ u16 g_win_h [3*EE*EE];
__device__ u16 g_wout_h[EE*EE];
__device__ u16 g_wfc_h [4*EE*EE];
__device__ u16 g_wpr_h [4*EE*EE];

// ---------------- helpers (fp16 split: x = hi + lo/2048) ----------------
__device__ __forceinline__ float h2f(u16 u){ return __half2float(__ushort_as_half(u)); }
__device__ __forceinline__ u16 f2h(float f){ return __half_as_ushort(__float2half_rn(f)); }
__device__ __forceinline__ u32 smem_u32(const void* p){
    u32 a; asm("{ .reg .u64 t; cvta.to.shared.u64 t, %1; cvt.u32.u64 %0, t; }" : "=r"(a) : "l"(p));
    return a;
}
__device__ __forceinline__ void cp16(u32 dst, const void* src){
    asm volatile("cp.async.cg.shared.global [%0], [%1], 16;\n" :: "r"(dst), "l"(src));
}
#define CP_COMMIT() asm volatile("cp.async.commit_group;\n" ::: "memory")
#define CP_WAIT0()  asm volatile("cp.async.wait_group 0;\n" ::: "memory")
#define CP_WAIT1()  asm volatile("cp.async.wait_group 1;\n" ::: "memory")

__device__ __forceinline__ void ldmx4(u32& r0, u32& r1, u32& r2, u32& r3, u32 addr){
    asm volatile("ldmatrix.sync.aligned.m8n8.x4.shared.b16 {%0,%1,%2,%3}, [%4];"
        : "=r"(r0),"=r"(r1),"=r"(r2),"=r"(r3) : "r"(addr));
}
__device__ __forceinline__ void ldmx2(u32& r0, u32& r1, u32 addr){
    asm volatile("ldmatrix.sync.aligned.m8n8.x2.shared.b16 {%0,%1}, [%2];"
        : "=r"(r0),"=r"(r1) : "r"(addr));
}
// f32-accumulator fp16 HMMA (main product)
__device__ __forceinline__ void mma16816(float* c, const u32* a, const u32* b){
    asm volatile("mma.sync.aligned.m16n8k16.row.col.f32.f16.f16.f32 "
        "{%0,%1,%2,%3}, {%4,%5,%6,%7}, {%8,%9}, {%0,%1,%2,%3};"
        : "+f"(c[0]),"+f"(c[1]),"+f"(c[2]),"+f"(c[3])
        : "r"(a[0]),"r"(a[1]),"r"(a[2]),"r"(a[3]), "r"(b[0]),"r"(b[1]));
}
// f16-accumulator fp16 HMMA (correction products)
__device__ __forceinline__ void mma16816h(u32* c, const u32* a, const u32* b){
    asm volatile("mma.sync.aligned.m16n8k16.row.col.f16.f16.f16.f16 "
        "{%0,%1}, {%2,%3,%4,%5}, {%6,%7}, {%0,%1};"
        : "+r"(c[0]),"+r"(c[1])
        : "r"(a[0]),"r"(a[1]),"r"(a[2]),"r"(a[3]), "r"(b[0]),"r"(b[1]));
}

// flags
#define FLAG_GELU   1
#define FLAG_CAUSAL 2
#define FLAG_CLIPK  4
#define FLAG_SPLIT  8
#define FLAG_HALF   16

// MODE: 0 = A split + B split (3 MMAs); 1 = A single + B split (2);
//       2 = A split + B single (2);    3 = A single + B single (1)
#define TM 128
#define KT 64
#define LDS_ROW 72          // 64 k-elems + 8 pad (144B row stride; conflict-free ldmatrix)

// ---------------- HMMA fp16-split GEMM ----------------
template<int TN, int MODE>
__global__ __launch_bounds__(256, 1)
void mma_gemm(const u16* __restrict__ Ahi, const u16* __restrict__ Alo, int lda,
              long long sAb, long long sAh,
              const u16* __restrict__ Bhi, const u16* __restrict__ Blo, int ldb,
              long long sBb, long long sBh,
              float* __restrict__ Cf, u16* __restrict__ Chi, u16* __restrict__ Clo, int ldc,
              long long sCb, long long sCh,
              const float* __restrict__ bias, const float* __restrict__ resid,
              int K, int Hdiv, float alpha, int flags)
{
    constexpr bool A_SPLIT = (MODE == 0 || MODE == 2);
    constexpr bool B_SPLIT = (MODE == 0 || MODE == 1);
    constexpr int WM = 4;                        // warp grid m (32-row warp tiles: low regs)
    constexpr int WN = 2;                        // warp grid n
    constexpr int MT = TM / (WM * 16);           // 2 m16 tiles per warp
    constexpr int NT = TN / (WN * 8);            // n8 tiles per warp
    constexpr int OA = TM * LDS_ROW;             // elems per A buf
    constexpr int OB = TN * LDS_ROW;
    constexpr int STG = 2*OA + 2*OB;             // elems per stage (layout fixed across modes)

    int m0 = blockIdx.y * TM;
    int n0 = blockIdx.x * TN;
    if ((flags & FLAG_CAUSAL) && n0 >= m0 + TM) return;   // fully masked tile

    int z  = blockIdx.z;
    int bb = z / Hdiv, hh = z % Hdiv;
    const u16* Ah = Ahi + bb*sAb + hh*sAh + (long long)m0*lda;
    const u16* Al = Alo + bb*sAb + hh*sAh + (long long)m0*lda;
    const u16* Bh = Bhi + bb*sBb + hh*sBh + (long long)n0*ldb;
    const u16* Bl = Blo + bb*sBb + hh*sBh + (long long)n0*ldb;

    int Keff = K;
    if (flags & FLAG_CLIPK) { int lim = m0 + TM; Keff = (lim < K) ? lim : K; }
    int T = Keff / KT;

    extern __shared__ __align__(128) u16 sm[];
    u32 sbase = smem_u32(sm);
    int tid = threadIdx.x;
    int lane = tid & 31, wid = tid >> 5;
    int warp_m = wid / WN, warp_n = wid % WN;

    auto load_tile = [&](int s, int k0){
        u32 base = sbase + s * STG * 2;
        for (int e = tid; e < TM*8; e += 256) {
            int r = e >> 3, c = e & 7;
            u32 off = (u32)(r*LDS_ROW*2 + c*16);
            long long g = (long long)r*lda + k0 + c*8;
            cp16(base + off, Ah + g);
            if (A_SPLIT) cp16(base + OA*2 + off, Al + g);
        }
        for (int e = tid; e < TN*8; e += 256) {
            int r = e >> 3, c = e & 7;
            u32 off = (u32)(r*LDS_ROW*2 + c*16);
            long long g = (long long)r*ldb + k0 + c*8;
            cp16(base + 4*OA + off, Bh + g);
            if (B_SPLIT) cp16(base + 4*OA + 2*OB + off, Bl + g);
        }
    };

    float acc[MT][NT][4];
    u32  acch[MT][NT][2];
    #pragma unroll
    for (int i = 0; i < MT; i++)
        #pragma unroll
        for (int j = 0; j < NT; j++) {
            #pragma unroll
            for (int q = 0; q < 4; q++) acc[i][j][q] = 0.f;
            acch[i][j][0] = 0u; acch[i][j][1] = 0u;
        }

    load_tile(0, 0); CP_COMMIT();

    for (int t = 0; t < T; ++t) {
        if (t + 1 < T) { load_tile((t+1) & 1, (t+1)*KT); CP_COMMIT(); CP_WAIT1(); }
        else           { CP_WAIT0(); }
        __syncthreads();

        int s = t & 1;
        u32 aHiB = sbase + s*STG*2;
        u32 aLoB = aHiB + OA*2;
        u32 bHiB = aHiB + 4*OA;
        u32 bLoB = bHiB + OB*2;

        #pragma unroll
        for (int ks = 0; ks < 4; ks++) {
            u32 aHi[MT][4], aLo[MT][4], bHi[NT][2], bLo[NT][2];
            #pragma unroll
            for (int mt = 0; mt < MT; mt++) {
                int row = warp_m*MT*16 + mt*16 + (lane & 15);
                u32 off = (u32)(row*LDS_ROW*2 + ks*32 + (lane >> 4)*16);
                ldmx4(aHi[mt][0], aHi[mt][1], aHi[mt][2], aHi[mt][3], aHiB + off);
                if (A_SPLIT) ldmx4(aLo[mt][0], aLo[mt][1], aLo[mt][2], aLo[mt][3], aLoB + off);
            }
            #pragma unroll
            for (int nt = 0; nt < NT; nt++) {
                int row = warp_n*NT*8 + nt*8 + (lane & 7);
                u32 off = (u32)(row*LDS_ROW*2 + ks*32 + ((lane >> 3) & 1)*16);
                ldmx2(bHi[nt][0], bHi[nt][1], bHiB + off);
                if (B_SPLIT) ldmx2(bLo[nt][0], bLo[nt][1], bLoB + off);
            }
            #pragma unroll
            for (int mt = 0; mt < MT; mt++)
                #pragma unroll
                for (int nt = 0; nt < NT; nt++) {
                    mma16816(acc[mt][nt], aHi[mt], bHi[nt]);                  // main, f32 acc
                    if (B_SPLIT) mma16816h(acch[mt][nt], aHi[mt], bLo[nt]);   // A·B_lo
                    if (A_SPLIT) mma16816h(acch[mt][nt], aLo[mt], bHi[nt]);   // A_lo·B
                }
        }
        __syncthreads();
    }

    // ---- epilogue (packed stores: lanes own (n, n+1) pairs) ----
    long long cb = bb*sCb + hh*sCh;
    #pragma unroll
    for (int mt = 0; mt < MT; mt++) {
        #pragma unroll
        for (int nt = 0; nt < NT; nt++) {
            int rr = m0 + warp_m*MT*16 + mt*16 + (lane >> 2);
            int nn = n0 + warp_n*NT*8 + nt*8 + (lane & 3)*2;
            #pragma unroll
            for (int half = 0; half < 2; half++) {
                int m = rr + half*8;
                long long crow = cb + (long long)m*ldc;
                float corr[2] = {0.f, 0.f};
                if (A_SPLIT || B_SPLIT) {
                    half2 hc = *reinterpret_cast<half2*>(&acch[mt][nt][half]);
                    corr[0] = __low2float(hc); corr[1] = __high2float(hc);
                }
                float v[2];
                #pragma unroll
                for (int j = 0; j < 2; j++) {
                    float vv = (acc[mt][nt][half*2 + j] + corr[j]*LO_INV) * alpha;
                    int n = nn + j;
                    if (bias)  vv += bias[n];
                    if (resid) vv += resid[crow + n];
                    if (flags & FLAG_GELU) {
                        float tg = tanhf(0.7978845608028654f * (vv + 0.044715f*vv*vv*vv));
                        vv = 0.5f * vv * (1.f + tg);
                    }
                    v[j] = vv;
                }
                if (flags & FLAG_SPLIT) {
                    u16 h0 = f2h(v[0]), h1 = f2h(v[1]);
                    u16 l0 = f2h((v[0] - h2f(h0))*LO_SCALE), l1 = f2h((v[1] - h2f(h1))*LO_SCALE);
                    *reinterpret_cast<u32*>(Chi + crow + nn) = (u32)h0 | ((u32)h1 << 16);
                    *reinterpret_cast<u32*>(Clo + crow + nn) = (u32)l0 | ((u32)l1 << 16);
                } else if (flags & FLAG_HALF) {
                    *reinterpret_cast<u32*>(Chi + crow + nn) = (u32)f2h(v[0]) | ((u32)f2h(v[1]) << 16);
                } else {
                    *reinterpret_cast<float2*>(Cf + crow + nn) = make_float2(v[0], v[1]);
                }
            }
        }
    }
}

// ---------------- LayerNorm -> single fp16 ----------------
__global__ void ln_half_kernel(const float* __restrict__ x,
                               const float* __restrict__ g,
                               const float* __restrict__ b,
                               u16* __restrict__ ohi)
{
    long long row = blockIdx.x;
    const float* xr = x + row * EE;
    __shared__ float red[256];
    int tid = threadIdx.x;

    float s = 0.f;
    for (int c = tid; c < EE; c += 256) s += xr[c];
    red[tid] = s; __syncthreads();
    for (int st = 128; st > 0; st >>= 1){ if (tid < st) red[tid] += red[tid+st]; __syncthreads(); }
    float mu = red[0] * (1.f/EE); __syncthreads();

    float v = 0.f;
    for (int c = tid; c < EE; c += 256){ float d = xr[c]-mu; v += d*d; }
    red[tid] = v; __syncthreads();
    for (int st = 128; st > 0; st >>= 1){ if (tid < st) red[tid] += red[tid+st]; __syncthreads(); }
    float inv = rsqrtf(red[0]*(1.f/EE) + LN_EPS); __syncthreads();

    for (int c = tid; c < EE; c += 256) {
        float o = (xr[c]-mu)*inv*g[c] + b[c];
        ohi[row*EE + c] = f2h(o);
    }
}

// ---------------- convert f32 -> fp16 (weights; single plane) ----------------
__global__ void cvt_kernel(const float* __restrict__ src, u16* __restrict__ dst, long long n)
{
    long long i = ((long long)blockIdx.x * 256 + threadIdx.x) * 4;
    if (i >= n) return;
    float4 v = *reinterpret_cast<const float4*>(src + i);
    u16 h[4] = { f2h(v.x), f2h(v.y), f2h(v.z), f2h(v.w) };
    *reinterpret_cast<u64*>(dst + i) = *(u64*)h;
}

// ---------------- transpose V (hi only): qkv[b,s, 2E + h*64 + d] -> vt[(b,h), d, s] ----------------
__global__ void transpose_v(const u16* __restrict__ qh, u16* __restrict__ vth)
{
    __shared__ u16 th[32][33];
    int bh = blockIdx.z; int b = bh >> 4, h = bh & 15;
    int s0 = blockIdx.x * 32, d0 = blockIdx.y * 32;
    int tx = threadIdx.x, ty = threadIdx.y;
    #pragma unroll
    for (int i = 0; i < 4; i++) {
        int s = s0 + ty + i*8;
        long long src = ((long long)(b*SS + s))*(3*EE) + 2*EE + h*DH + d0 + tx;
        th[ty + i*8][tx] = qh[src];
    }
    __syncthreads();
    #pragma unroll
    for (int i = 0; i < 4; i++) {
        int d = d0 + ty + i*8;
        long long dst = ((long long)(bh*DH + d))*SS + s0 + tx;
        vth[dst] = th[tx][ty + i*8];
    }
}

// ---------------- fused causal softmax (all heads) + att_weights ----------------
// One block per (b, q). Probs written (single fp16) only to k < (q/128+1)*128.
__global__ void softmax_attw(u16* __restrict__ ph, const u16* __restrict__ pl,
                             float* __restrict__ outw)
{
    int bq = blockIdx.x;            // b*SS + q
    int b = bq >> 10, q = bq & (SS-1);
    int Lw = ((q >> 7) + 1) << 7;   // write length (multiple of 128)
    int tid = threadIdx.x;          // 256
    __shared__ float row[SS];
    __shared__ float red[256];
    float aw[4] = {0.f, 0.f, 0.f, 0.f};

    for (int h = 0; h < HH; h++) {
        long long base = (((long long)(b*HH + h)) << 20) | ((long long)q << 10);
        float mx = -1e30f;
        for (int c = tid; c <= q; c += 256) {
            float v = h2f(ph[base+c]) + h2f(pl[base+c])*LO_INV;
            row[c] = v;
            mx = fmaxf(mx, v);
        }
        red[tid] = mx; __syncthreads();
        for (int st = 128; st > 0; st >>= 1){ if (tid < st) red[tid] = fmaxf(red[tid], red[tid+st]); __syncthreads(); }
        mx = red[0]; __syncthreads();

        float sum = 0.f;
        for (int c = tid; c <= q; c += 256){ float e = __expf(row[c]-mx); row[c] = e; sum += e; }
        red[tid] = sum; __syncthreads();
        for (int st = 128; st > 0; st >>= 1){ if (tid < st) red[tid] += red[tid+st]; __syncthreads(); }
        float inv = 1.f / red[0]; __syncthreads();

        for (int c = tid; c < Lw; c += 256) {
            float p = (c <= q) ? row[c]*inv : 0.f;
            ph[base+c] = f2h(p);
            aw[c >> 8] += p;
        }
    }
    long long ob = ((long long)bq) << 10;
    #pragma unroll
    for (int i = 0; i < 4; i++) {
        int c = tid + 256*i;
        outw[ob + c] = (c <= q) ? aw[i]*(1.f/HH) : 0.f;
    }
}

// ---------------- launch ----------------
extern "C" void kernel_launch(void* const* d_in, const int* in_sizes, int n_in,
                              void* d_out, int out_size)
{
    const float* x      = (const float*)d_in[0];
    const float* ln1_g  = (const float*)d_in[2];
    const float* ln1_b  = (const float*)d_in[3];
    const float* ln2_g  = (const float*)d_in[4];
    const float* ln2_b  = (const float*)d_in[5];
    const float* w_in   = (const float*)d_in[6];
    const float* b_in   = (const float*)d_in[7];
    const float* w_out  = (const float*)d_in[8];
    const float* b_out  = (const float*)d_in[9];
    const float* w_fc   = (const float*)d_in[10];
    const float* b_fc   = (const float*)d_in[11];
    const float* w_proj = (const float*)d_in[12];
    const float* b_proj = (const float*)d_in[13];

    float* out_x = (float*)d_out;
    float* out_w = (float*)d_out + (long long)ROWS*EE;

    u16 *h_hi,*qkv_hi,*qkv_lo,*vt_hi,*p_hi,*p_lo,*att_hi,*h2_hi,*fc_hi;
    u16 *win_h,*wout_h,*wfc_h,*wpr_h;
    float *x1;
    cudaGetSymbolAddress((void**)&h_hi, g_h_hi);
    cudaGetSymbolAddress((void**)&qkv_hi, g_qkv_hi); cudaGetSymbolAddress((void**)&qkv_lo, g_qkv_lo);
    cudaGetSymbolAddress((void**)&vt_hi, g_vt_hi);
    cudaGetSymbolAddress((void**)&p_hi, g_p_hi);     cudaGetSymbolAddress((void**)&p_lo, g_p_lo);
    cudaGetSymbolAddress((void**)&att_hi, g_att_hi);
    cudaGetSymbolAddress((void**)&x1, g_x1);
    cudaGetSymbolAddress((void**)&h2_hi, g_h2_hi);
    cudaGetSymbolAddress((void**)&fc_hi, g_fc_hi);
    cudaGetSymbolAddress((void**)&win_h, g_win_h);
    cudaGetSymbolAddress((void**)&wout_h, g_wout_h);
    cudaGetSymbolAddress((void**)&wfc_h, g_wfc_h);
    cudaGetSymbolAddress((void**)&wpr_h, g_wpr_h);

    const int SM128 = 2 * (2*TM*LDS_ROW + 2*128*LDS_ROW) * 2;   // 147456
    const int SM64  = 2 * (2*TM*LDS_ROW + 2*64*LDS_ROW) * 2;    // 110592
    cudaFuncSetAttribute((const void*)mma_gemm<128,0>, cudaFuncAttributeMaxDynamicSharedMemorySize, SM128);
    cudaFuncSetAttribute((const void*)mma_gemm<128,3>, cudaFuncAttributeMaxDynamicSharedMemorySize, SM128);
    cudaFuncSetAttribute((const void*)mma_gemm<64,3>,  cudaFuncAttributeMaxDynamicSharedMemorySize, SM64);

    const long long SSS = (long long)SS*SS;

    // 0) convert weights -> single fp16
    cvt_kernel<<<3*EE*EE/4/256, 256>>>(w_in,   win_h, 3*EE*EE);
    cvt_kernel<<<EE*EE/4/256,   256>>>(w_out,  wout_h, EE*EE);
    cvt_kernel<<<4*EE*EE/4/256, 256>>>(w_fc,   wfc_h, 4*EE*EE);
    cvt_kernel<<<4*EE*EE/4/256, 256>>>(w_proj, wpr_h, 4*EE*EE);

    // 1) LN1 -> single fp16
    ln_half_kernel<<<ROWS, 256>>>(x, ln1_g, ln1_b, h_hi);

    // 2) QKV = h @ w_in^T + b_in (single x single, 1 MMA) -> split (for scores)
    mma_gemm<128,3><<<dim3(24, 32, 1), 256, SM128>>>(
        h_hi, h_hi, EE, 0, 0,
        win_h, win_h, EE, 0, 0,
        nullptr, qkv_hi, qkv_lo, 3*EE, 0, 0,
        b_in, nullptr, EE, 1, 1.f, FLAG_SPLIT);

    // 3) V transpose (hi only)
    transpose_v<<<dim3(SS/32, DH/32, BB*HH), dim3(32,8)>>>(qkv_hi, vt_hi);

    // 4) scores = 0.125 * q @ k^T (both split, 3 MMAs; masked tiles skipped) -> split
    mma_gemm<128,0><<<dim3(8, 8, BB*HH), 256, SM128>>>(
        qkv_hi, qkv_lo, 3*EE, (long long)SS*3*EE, DH,
        qkv_hi + EE, qkv_lo + EE, 3*EE, (long long)SS*3*EE, DH,
        nullptr, p_hi, p_lo, SS, (long long)HH*SSS, SSS,
        nullptr, nullptr, DH, HH, 0.125f, FLAG_CAUSAL | FLAG_SPLIT);

    // 5+6) fused softmax + att_weights (probs -> single fp16 in p_hi)
    softmax_attw<<<ROWS, 256>>>(p_hi, p_lo, out_w);

    // 7) att = P @ V^T (single x single; K clipped causally) -> single fp16
    mma_gemm<64,3><<<dim3(1, 8, BB*HH), 256, SM64>>>(
        p_hi, p_hi, SS, (long long)HH*SSS, SSS,
        vt_hi, vt_hi, SS, (long long)HH*DH*SS, (long long)DH*SS,
        nullptr, att_hi, nullptr, EE, (long long)SS*EE, DH,
        nullptr, nullptr, SS, HH, 1.f, FLAG_CLIPK | FLAG_HALF);

    // 8) x1 = x + att @ w_out^T + b_out (single x single; f32 out)
    mma_gemm<128,3><<<dim3(8, 32, 1), 256, SM128>>>(
        att_hi, att_hi, EE, 0, 0,
        wout_h, wout_h, EE, 0, 0,
        x1, nullptr, nullptr, EE, 0, 0,
        b_out, x, EE, 1, 1.f, 0);

    // 9) LN2 -> single fp16
    ln_half_kernel<<<ROWS, 256>>>(x1, ln2_g, ln2_b, h2_hi);

    // 10) fc = gelu(h2 @ w_fc^T + b_fc) (single x single) -> single fp16
    mma_gemm<128,3><<<dim3(32, 32, 1), 256, SM128>>>(
        h2_hi, h2_hi, EE, 0, 0,
        wfc_h, wfc_h, EE, 0, 0,
        nullptr, fc_hi, nullptr, 4*EE, 0, 0,
        b_fc, nullptr, EE, 1, 1.f, FLAG_HALF | FLAG_GELU);

    // 11) out_x = x1 + fc @ w_proj^T + b_proj (single x single; f32 out)
    mma_gemm<128,3><<<dim3(8, 32, 1), 256, SM128>>>(
        fc_hi, fc_hi, 4*EE, 0, 0,
        wpr_h, wpr_h, 4*EE, 0, 0,
        out_x, nullptr, nullptr, EE, 0, 0,
        b_proj, x1, 4*EE, 1, 1.f, 0);
}

// round 14
// speedup vs baseline: 2.9356x; 1.1921x over previous
#include <cuda_runtime.h>
#include <cuda_fp16.h>
#include <math.h>
#include <stdint.h>

#define BB 4
#define SS 1024
#define EE 1024
#define HH 16
#define DH 64
#define ROWS (BB*SS)
#define LN_EPS 1e-5f

typedef unsigned short u16;
typedef unsigned int   u32;
typedef unsigned long long u64;

// ---------------- scratch (device globals; no allocation allowed) ----------------
__device__ u16 g_h_hi [ROWS*EE];
__device__ u16 g_qkv_hi[ROWS*3*EE];
__device__ u16 g_vt_hi[BB*HH*DH*SS];
__device__ u16 g_p_hi[(long long)BB*HH*SS*SS];
__device__ u16 g_att_hi[ROWS*EE];
__device__ float g_x1[ROWS*EE];
__device__ u16 g_h2_hi[ROWS*EE];
__device__ u16 g_fc_hi[ROWS*4*EE];
__device__ u16 g_win_h [3*EE*EE];
__device__ u16 g_wout_h[EE*EE];
__device__ u16 g_wfc_h [4*EE*EE];
__device__ u16 g_wpr_h [4*EE*EE];

// ---------------- helpers ----------------
__device__ __forceinline__ float h2f(u16 u){ return __half2float(__ushort_as_half(u)); }
__device__ __forceinline__ u16 f2h(float f){ return __half_as_ushort(__float2half_rn(f)); }
__device__ __forceinline__ u32 smem_u32(const void* p){
    u32 a; asm("{ .reg .u64 t; cvta.to.shared.u64 t, %1; cvt.u32.u64 %0, t; }" : "=r"(a) : "l"(p));
    return a;
}
__device__ __forceinline__ void cp16(u32 dst, const void* src){
    asm volatile("cp.async.cg.shared.global [%0], [%1], 16;\n" :: "r"(dst), "l"(src));
}
#define CP_COMMIT() asm volatile("cp.async.commit_group;\n" ::: "memory")
#define CP_WAIT0()  asm volatile("cp.async.wait_group 0;\n" ::: "memory")
#define CP_WAIT1()  asm volatile("cp.async.wait_group 1;\n" ::: "memory")

__device__ __forceinline__ void ldmx4(u32& r0, u32& r1, u32& r2, u32& r3, u32 addr){
    asm volatile("ldmatrix.sync.aligned.m8n8.x4.shared.b16 {%0,%1,%2,%3}, [%4];"
        : "=r"(r0),"=r"(r1),"=r"(r2),"=r"(r3) : "r"(addr));
}
__device__ __forceinline__ void ldmx2(u32& r0, u32& r1, u32 addr){
    asm volatile("ldmatrix.sync.aligned.m8n8.x2.shared.b16 {%0,%1}, [%2];"
        : "=r"(r0),"=r"(r1) : "r"(addr));
}
__device__ __forceinline__ void mma16816(float* c, const u32* a, const u32* b){
    asm volatile("mma.sync.aligned.m16n8k16.row.col.f32.f16.f16.f32 "
        "{%0,%1,%2,%3}, {%4,%5,%6,%7}, {%8,%9}, {%0,%1,%2,%3};"
        : "+f"(c[0]),"+f"(c[1]),"+f"(c[2]),"+f"(c[3])
        : "r"(a[0]),"r"(a[1]),"r"(a[2]),"r"(a[3]), "r"(b[0]),"r"(b[1]));
}

// flags
#define FLAG_GELU   1
#define FLAG_CAUSAL 2
#define FLAG_CLIPK  4
#define FLAG_HALF   16

#define TM 128
#define KT 64
#define LDS_ROW 72          // 64 k-elems + 8 pad (144B row stride; conflict-free ldmatrix)

// ---------------- HMMA single-fp16 GEMM (1 MMA per tile-pair) ----------------
// C = alpha * A·B^T (+bias/+resid/gelu).  A [M,K], B [N,K] K-major fp16.
template<int TN>
__global__ __launch_bounds__(256, 1)
void mma_gemm(const u16* __restrict__ Ahi, int lda, long long sAb, long long sAh,
              const u16* __restrict__ Bhi, int ldb, long long sBb, long long sBh,
              float* __restrict__ Cf, u16* __restrict__ Chi, int ldc,
              long long sCb, long long sCh,
              const float* __restrict__ bias, const float* __restrict__ resid,
              int K, int Hdiv, float alpha, int flags)
{
    constexpr int WM = 4;                        // warp grid m
    constexpr int WN = 2;                        // warp grid n
    constexpr int MT = TM / (WM * 16);           // 2 m16 tiles per warp
    constexpr int NT = TN / (WN * 8);            // n8 tiles per warp
    constexpr int OA = TM * LDS_ROW;
    constexpr int OB = TN * LDS_ROW;
    constexpr int STG = OA + OB;                 // elems per stage (single planes only)

    int m0 = blockIdx.y * TM;
    int n0 = blockIdx.x * TN;
    if ((flags & FLAG_CAUSAL) && n0 >= m0 + TM) return;

    int z  = blockIdx.z;
    int bb = z / Hdiv, hh = z % Hdiv;
    const u16* Ah = Ahi + bb*sAb + hh*sAh + (long long)m0*lda;
    const u16* Bh = Bhi + bb*sBb + hh*sBh + (long long)n0*ldb;

    int Keff = K;
    if (flags & FLAG_CLIPK) { int lim = m0 + TM; Keff = (lim < K) ? lim : K; }
    int T = Keff / KT;

    extern __shared__ __align__(128) u16 sm[];
    u32 sbase = smem_u32(sm);
    int tid = threadIdx.x;
    int lane = tid & 31, wid = tid >> 5;
    int warp_m = wid / WN, warp_n = wid % WN;

    auto load_tile = [&](int s, int k0){
        u32 base = sbase + s * STG * 2;
        for (int e = tid; e < TM*8; e += 256) {
            int r = e >> 3, c = e & 7;
            cp16(base + (u32)(r*LDS_ROW*2 + c*16), Ah + (long long)r*lda + k0 + c*8);
        }
        for (int e = tid; e < TN*8; e += 256) {
            int r = e >> 3, c = e & 7;
            cp16(base + 2*OA + (u32)(r*LDS_ROW*2 + c*16), Bh + (long long)r*ldb + k0 + c*8);
        }
    };

    float acc[MT][NT][4];
    #pragma unroll
    for (int i = 0; i < MT; i++)
        #pragma unroll
        for (int j = 0; j < NT; j++)
            #pragma unroll
            for (int q = 0; q < 4; q++) acc[i][j][q] = 0.f;

    load_tile(0, 0); CP_COMMIT();

    for (int t = 0; t < T; ++t) {
        if (t + 1 < T) { load_tile((t+1) & 1, (t+1)*KT); CP_COMMIT(); CP_WAIT1(); }
        else           { CP_WAIT0(); }
        __syncthreads();

        int s = t & 1;
        u32 aB = sbase + s*STG*2;
        u32 bB = aB + 2*OA;

        #pragma unroll
        for (int ks = 0; ks < 4; ks++) {
            u32 aF[MT][4], bF[NT][2];
            #pragma unroll
            for (int mt = 0; mt < MT; mt++) {
                int row = warp_m*MT*16 + mt*16 + (lane & 15);
                u32 off = (u32)(row*LDS_ROW*2 + ks*32 + (lane >> 4)*16);
                ldmx4(aF[mt][0], aF[mt][1], aF[mt][2], aF[mt][3], aB + off);
            }
            #pragma unroll
            for (int nt = 0; nt < NT; nt++) {
                int row = warp_n*NT*8 + nt*8 + (lane & 7);
                u32 off = (u32)(row*LDS_ROW*2 + ks*32 + ((lane >> 3) & 1)*16);
                ldmx2(bF[nt][0], bF[nt][1], bB + off);
            }
            #pragma unroll
            for (int mt = 0; mt < MT; mt++)
                #pragma unroll
                for (int nt = 0; nt < NT; nt++)
                    mma16816(acc[mt][nt], aF[mt], bF[nt]);
        }
        __syncthreads();
    }

    // ---- epilogue (packed stores: lanes own (n, n+1) pairs) ----
    long long cb = bb*sCb + hh*sCh;
    #pragma unroll
    for (int mt = 0; mt < MT; mt++) {
        #pragma unroll
        for (int nt = 0; nt < NT; nt++) {
            int rr = m0 + warp_m*MT*16 + mt*16 + (lane >> 2);
            int nn = n0 + warp_n*NT*8 + nt*8 + (lane & 3)*2;
            #pragma unroll
            for (int half = 0; half < 2; half++) {
                int m = rr + half*8;
                long long crow = cb + (long long)m*ldc;
                float v[2];
                #pragma unroll
                for (int j = 0; j < 2; j++) {
                    float vv = acc[mt][nt][half*2 + j] * alpha;
                    int n = nn + j;
                    if (bias)  vv += bias[n];
                    if (resid) vv += resid[crow + n];
                    if (flags & FLAG_GELU) {
                        float tg = tanhf(0.7978845608028654f * (vv + 0.044715f*vv*vv*vv));
                        vv = 0.5f * vv * (1.f + tg);
                    }
                    v[j] = vv;
                }
                if (flags & FLAG_HALF) {
                    *reinterpret_cast<u32*>(Chi + crow + nn) = (u32)f2h(v[0]) | ((u32)f2h(v[1]) << 16);
                } else {
                    *reinterpret_cast<float2*>(Cf + crow + nn) = make_float2(v[0], v[1]);
                }
            }
        }
    }
}

// ---------------- LayerNorm -> single fp16 ----------------
__global__ void ln_half_kernel(const float* __restrict__ x,
                               const float* __restrict__ g,
                               const float* __restrict__ b,
                               u16* __restrict__ ohi)
{
    long long row = blockIdx.x;
    const float* xr = x + row * EE;
    __shared__ float red[256];
    int tid = threadIdx.x;

    float s = 0.f;
    for (int c = tid; c < EE; c += 256) s += xr[c];
    red[tid] = s; __syncthreads();
    for (int st = 128; st > 0; st >>= 1){ if (tid < st) red[tid] += red[tid+st]; __syncthreads(); }
    float mu = red[0] * (1.f/EE); __syncthreads();

    float v = 0.f;
    for (int c = tid; c < EE; c += 256){ float d = xr[c]-mu; v += d*d; }
    red[tid] = v; __syncthreads();
    for (int st = 128; st > 0; st >>= 1){ if (tid < st) red[tid] += red[tid+st]; __syncthreads(); }
    float inv = rsqrtf(red[0]*(1.f/EE) + LN_EPS); __syncthreads();

    for (int c = tid; c < EE; c += 256) {
        float o = (xr[c]-mu)*inv*g[c] + b[c];
        ohi[row*EE + c] = f2h(o);
    }
}

// ---------------- convert f32 -> fp16 ----------------
__global__ void cvt_kernel(const float* __restrict__ src, u16* __restrict__ dst, long long n)
{
    long long i = ((long long)blockIdx.x * 256 + threadIdx.x) * 4;
    if (i >= n) return;
    float4 v = *reinterpret_cast<const float4*>(src + i);
    u16 h[4] = { f2h(v.x), f2h(v.y), f2h(v.z), f2h(v.w) };
    *reinterpret_cast<u64*>(dst + i) = *(u64*)h;
}

// ---------------- transpose V: qkv[b,s, 2E + h*64 + d] -> vt[(b,h), d, s] ----------------
__global__ void transpose_v(const u16* __restrict__ qh, u16* __restrict__ vth)
{
    __shared__ u16 th[32][33];
    int bh = blockIdx.z; int b = bh >> 4, h = bh & 15;
    int s0 = blockIdx.x * 32, d0 = blockIdx.y * 32;
    int tx = threadIdx.x, ty = threadIdx.y;
    #pragma unroll
    for (int i = 0; i < 4; i++) {
        int s = s0 + ty + i*8;
        long long src = ((long long)(b*SS + s))*(3*EE) + 2*EE + h*DH + d0 + tx;
        th[ty + i*8][tx] = qh[src];
    }
    __syncthreads();
    #pragma unroll
    for (int i = 0; i < 4; i++) {
        int d = d0 + ty + i*8;
        long long dst = ((long long)(bh*DH + d))*SS + s0 + tx;
        vth[dst] = th[tx][ty + i*8];
    }
}

// ---------------- warp-per-head causal softmax + att_weights ----------------
// Block = (b,q); 8 warps; warp w handles heads w, w+8. No block syncs in head loop.
__global__ __launch_bounds__(256)
void softmax_attw(u16* __restrict__ ph, float* __restrict__ outw)
{
    int bq = blockIdx.x;
    int b = bq >> 10, q = bq & (SS-1);
    int tid = threadIdx.x, lane = tid & 31, w = tid >> 5;
    int Lw = ((q >> 7) + 1) << 7;            // write length (multiple of 128)
    __shared__ float aw[SS];
    for (int c = tid; c < SS; c += 256) aw[c] = 0.f;
    __syncthreads();

    for (int hh = w; hh < HH; hh += 8) {
        long long base = (((long long)(b*HH + hh)) << 20) | ((long long)q << 10);
        float vals[32];
        float mx = -1e30f;
        #pragma unroll
        for (int i = 0; i < 32; i++) {
            int c0 = i << 5;
            if (c0 <= q) {
                int c = c0 + lane;
                float v = (c <= q) ? h2f(ph[base + c]) : -1e30f;
                vals[i] = v;
                mx = fmaxf(mx, v);
            }
        }
        #pragma unroll
        for (int o = 16; o > 0; o >>= 1) mx = fmaxf(mx, __shfl_xor_sync(0xFFFFFFFFu, mx, o));

        float sum = 0.f;
        #pragma unroll
        for (int i = 0; i < 32; i++) {
            int c0 = i << 5;
            if (c0 <= q) {
                int c = c0 + lane;
                float e = (c <= q) ? __expf(vals[i] - mx) : 0.f;
                vals[i] = e;
                sum += e;
            }
        }
        #pragma unroll
        for (int o = 16; o > 0; o >>= 1) sum += __shfl_xor_sync(0xFFFFFFFFu, sum, o);
        float inv = 1.f / sum;

        #pragma unroll
        for (int i = 0; i < 32; i++) {
            int c0 = i << 5;
            if (c0 < Lw) {
                int c = c0 + lane;
                float p = (c <= q) ? vals[i]*inv : 0.f;
                ph[base + c] = f2h(p);
                if (p != 0.f) atomicAdd(&aw[c], p);
            }
        }
    }
    __syncthreads();
    long long ob = ((long long)bq) << 10;
    #pragma unroll
    for (int j = 0; j < 4; j++) {
        int c = tid + 256*j;
        outw[ob + c] = aw[c] * (1.f/HH);
    }
}

// ---------------- launch ----------------
extern "C" void kernel_launch(void* const* d_in, const int* in_sizes, int n_in,
                              void* d_out, int out_size)
{
    const float* x      = (const float*)d_in[0];
    const float* ln1_g  = (const float*)d_in[2];
    const float* ln1_b  = (const float*)d_in[3];
    const float* ln2_g  = (const float*)d_in[4];
    const float* ln2_b  = (const float*)d_in[5];
    const float* w_in   = (const float*)d_in[6];
    const float* b_in   = (const float*)d_in[7];
    const float* w_out  = (const float*)d_in[8];
    const float* b_out  = (const float*)d_in[9];
    const float* w_fc   = (const float*)d_in[10];
    const float* b_fc   = (const float*)d_in[11];
    const float* w_proj = (const float*)d_in[12];
    const float* b_proj = (const float*)d_in[13];

    float* out_x = (float*)d_out;
    float* out_w = (float*)d_out + (long long)ROWS*EE;

    u16 *h_hi,*qkv_hi,*vt_hi,*p_hi,*att_hi,*h2_hi,*fc_hi;
    u16 *win_h,*wout_h,*wfc_h,*wpr_h;
    float *x1;
    cudaGetSymbolAddress((void**)&h_hi, g_h_hi);
    cudaGetSymbolAddress((void**)&qkv_hi, g_qkv_hi);
    cudaGetSymbolAddress((void**)&vt_hi, g_vt_hi);
    cudaGetSymbolAddress((void**)&p_hi, g_p_hi);
    cudaGetSymbolAddress((void**)&att_hi, g_att_hi);
    cudaGetSymbolAddress((void**)&x1, g_x1);
    cudaGetSymbolAddress((void**)&h2_hi, g_h2_hi);
    cudaGetSymbolAddress((void**)&fc_hi, g_fc_hi);
    cudaGetSymbolAddress((void**)&win_h, g_win_h);
    cudaGetSymbolAddress((void**)&wout_h, g_wout_h);
    cudaGetSymbolAddress((void**)&wfc_h, g_wfc_h);
    cudaGetSymbolAddress((void**)&wpr_h, g_wpr_h);

    const int SM128 = 2 * (TM*LDS_ROW + 128*LDS_ROW) * 2;   // 73728
    const int SM64  = 2 * (TM*LDS_ROW + 64*LDS_ROW) * 2;    // 55296
    cudaFuncSetAttribute((const void*)mma_gemm<128>, cudaFuncAttributeMaxDynamicSharedMemorySize, SM128);
    cudaFuncSetAttribute((const void*)mma_gemm<64>,  cudaFuncAttributeMaxDynamicSharedMemorySize, SM64);

    const long long SSS = (long long)SS*SS;

    // 0) convert weights -> fp16
    cvt_kernel<<<3*EE*EE/4/256, 256>>>(w_in,   win_h, 3*EE*EE);
    cvt_kernel<<<EE*EE/4/256,   256>>>(w_out,  wout_h, EE*EE);
    cvt_kernel<<<4*EE*EE/4/256, 256>>>(w_fc,   wfc_h, 4*EE*EE);
    cvt_kernel<<<4*EE*EE/4/256, 256>>>(w_proj, wpr_h, 4*EE*EE);

    // 1) LN1 -> fp16
    ln_half_kernel<<<ROWS, 256>>>(x, ln1_g, ln1_b, h_hi);

    // 2) QKV = h @ w_in^T + b_in -> fp16
    mma_gemm<128><<<dim3(24, 32, 1), 256, SM128>>>(
        h_hi, EE, 0, 0,
        win_h, EE, 0, 0,
        nullptr, qkv_hi, 3*EE, 0, 0,
        b_in, nullptr, EE, 1, 1.f, FLAG_HALF);

    // 3) V transpose
    transpose_v<<<dim3(SS/32, DH/32, BB*HH), dim3(32,8)>>>(qkv_hi, vt_hi);

    // 4) scores = 0.125 * q @ k^T (masked tiles skipped) -> fp16
    mma_gemm<128><<<dim3(8, 8, BB*HH), 256, SM128>>>(
        qkv_hi, 3*EE, (long long)SS*3*EE, DH,
        qkv_hi + EE, 3*EE, (long long)SS*3*EE, DH,
        nullptr, p_hi, SS, (long long)HH*SSS, SSS,
        nullptr, nullptr, DH, HH, 0.125f, FLAG_CAUSAL | FLAG_HALF);

    // 5+6) warp-per-head softmax + att_weights (in-place fp16 probs)
    softmax_attw<<<ROWS, 256>>>(p_hi, out_w);

    // 7) att = P @ V^T (K clipped causally) -> fp16
    mma_gemm<64><<<dim3(1, 8, BB*HH), 256, SM64>>>(
        p_hi, SS, (long long)HH*SSS, SSS,
        vt_hi, SS, (long long)HH*DH*SS, (long long)DH*SS,
        nullptr, att_hi, EE, (long long)SS*EE, DH,
        nullptr, nullptr, SS, HH, 1.f, FLAG_CLIPK | FLAG_HALF);

    // 8) x1 = x + att @ w_out^T + b_out (f32 out)
    mma_gemm<128><<<dim3(8, 32, 1), 256, SM128>>>(
        att_hi, EE, 0, 0,
        wout_h, EE, 0, 0,
        x1, nullptr, EE, 0, 0,
        b_out, x, EE, 1, 1.f, 0);

    // 9) LN2 -> fp16
    ln_half_kernel<<<ROWS, 256>>>(x1, ln2_g, ln2_b, h2_hi);

    // 10) fc = gelu(h2 @ w_fc^T + b_fc) -> fp16
    mma_gemm<128><<<dim3(32, 32, 1), 256, SM128>>>(
        h2_hi, EE, 0, 0,
        wfc_h, EE, 0, 0,
        nullptr, fc_hi, 4*EE, 0, 0,
        b_fc, nullptr, EE, 1, 1.f, FLAG_HALF | FLAG_GELU);

    // 11) out_x = x1 + fc @ w_proj^T + b_proj (f32 out)
    mma_gemm<128><<<dim3(8, 32, 1), 256, SM128>>>(
        fc_hi, 4*EE, 0, 0,
        wpr_h, 4*EE, 0, 0,
        out_x, nullptr, EE, 0, 0,
        b_proj, x1, 4*EE, 1, 1.f, 0);
}

// round 15
// speedup vs baseline: 3.3502x; 1.1413x over previous
#include <cuda_runtime.h>
#include <cuda_fp16.h>
#include <math.h>
#include <stdint.h>

#define BB 4
#define SS 1024
#define EE 1024
#define HH 16
#define DH 64
#define ROWS (BB*SS)
#define LN_EPS 1e-5f

typedef unsigned short u16;
typedef unsigned int   u32;
typedef unsigned long long u64;

// ---------------- scratch (device globals; no allocation allowed) ----------------
__device__ u16 g_h_hi [ROWS*EE];
__device__ u16 g_qkv_hi[ROWS*3*EE];
__device__ u16 g_vt_hi[BB*HH*DH*SS];
__device__ u16 g_p_hi[(long long)BB*HH*SS*SS];
__device__ u16 g_att_hi[ROWS*EE];
__device__ float g_x1[ROWS*EE];
__device__ u16 g_h2_hi[ROWS*EE];
__device__ u16 g_fc_hi[ROWS*4*EE];
__device__ u16 g_win_h [3*EE*EE];
__device__ u16 g_wout_h[EE*EE];
__device__ u16 g_wfc_h [4*EE*EE];
__device__ u16 g_wpr_h [4*EE*EE];

// ---------------- helpers ----------------
__device__ __forceinline__ float h2f(u16 u){ return __half2float(__ushort_as_half(u)); }
__device__ __forceinline__ u16 f2h(float f){ return __half_as_ushort(__float2half_rn(f)); }
__device__ __forceinline__ u32 smem_u32(const void* p){
    u32 a; asm("{ .reg .u64 t; cvta.to.shared.u64 t, %1; cvt.u32.u64 %0, t; }" : "=r"(a) : "l"(p));
    return a;
}
__device__ __forceinline__ void cp16(u32 dst, const void* src){
    asm volatile("cp.async.cg.shared.global [%0], [%1], 16;\n" :: "r"(dst), "l"(src));
}
#define CP_COMMIT() asm volatile("cp.async.commit_group;\n" ::: "memory")
#define CP_WAIT0()  asm volatile("cp.async.wait_group 0;\n" ::: "memory")
#define CP_WAIT1()  asm volatile("cp.async.wait_group 1;\n" ::: "memory")

__device__ __forceinline__ void ldmx4(u32& r0, u32& r1, u32& r2, u32& r3, u32 addr){
    asm volatile("ldmatrix.sync.aligned.m8n8.x4.shared.b16 {%0,%1,%2,%3}, [%4];"
        : "=r"(r0),"=r"(r1),"=r"(r2),"=r"(r3) : "r"(addr));
}
__device__ __forceinline__ void ldmx2(u32& r0, u32& r1, u32 addr){
    asm volatile("ldmatrix.sync.aligned.m8n8.x2.shared.b16 {%0,%1}, [%2];"
        : "=r"(r0),"=r"(r1) : "r"(addr));
}
__device__ __forceinline__ void mma16816(float* c, const u32* a, const u32* b){
    asm volatile("mma.sync.aligned.m16n8k16.row.col.f32.f16.f16.f32 "
        "{%0,%1,%2,%3}, {%4,%5,%6,%7}, {%8,%9}, {%0,%1,%2,%3};"
        : "+f"(c[0]),"+f"(c[1]),"+f"(c[2]),"+f"(c[3])
        : "r"(a[0]),"r"(a[1]),"r"(a[2]),"r"(a[3]), "r"(b[0]),"r"(b[1]));
}

// flags
#define FLAG_GELU   1
#define FLAG_CAUSAL 2
#define FLAG_CLIPK  4
#define FLAG_HALF   16

#define TM 128
#define KT 64
#define LDS_ROW 72          // 64 k-elems + 8 pad (144B row stride; conflict-free ldmatrix)

// ---------------- HMMA single-fp16 GEMM ----------------
// Warp grid 2x4: warp tile 64x32 (MT=4, NT=TN/32). 8 LDSM : 16 HMMA per k16.
template<int TN>
__global__ __launch_bounds__(256, 2)
void mma_gemm(const u16* __restrict__ Ahi, int lda, long long sAb, long long sAh,
              const u16* __restrict__ Bhi, int ldb, long long sBb, long long sBh,
              float* __restrict__ Cf, u16* __restrict__ Chi, int ldc,
              long long sCb, long long sCh,
              const float* __restrict__ bias, const float* __restrict__ resid,
              int K, int Hdiv, float alpha, int flags)
{
    constexpr int WM = 2;                        // warp grid m
    constexpr int WN = 4;                        // warp grid n
    constexpr int MT = TM / (WM * 16);           // 4 m16 tiles per warp
    constexpr int NT = TN / (WN * 8);            // n8 tiles per warp (4 for TN=128, 2 for 64)
    constexpr int OA = TM * LDS_ROW;
    constexpr int OB = TN * LDS_ROW;
    constexpr int STG = OA + OB;

    int m0 = blockIdx.y * TM;
    int n0 = blockIdx.x * TN;
    if ((flags & FLAG_CAUSAL) && n0 >= m0 + TM) return;

    int z  = blockIdx.z;
    int bb = z / Hdiv, hh = z % Hdiv;
    const u16* Ah = Ahi + bb*sAb + hh*sAh + (long long)m0*lda;
    const u16* Bh = Bhi + bb*sBb + hh*sBh + (long long)n0*ldb;

    int Keff = K;
    if (flags & FLAG_CLIPK) { int lim = m0 + TM; Keff = (lim < K) ? lim : K; }
    int T = Keff / KT;

    extern __shared__ __align__(128) u16 sm[];
    u32 sbase = smem_u32(sm);
    int tid = threadIdx.x;
    int lane = tid & 31, wid = tid >> 5;
    int warp_m = wid / WN, warp_n = wid % WN;

    auto load_tile = [&](int s, int k0){
        u32 base = sbase + s * STG * 2;
        for (int e = tid; e < TM*8; e += 256) {
            int r = e >> 3, c = e & 7;
            cp16(base + (u32)(r*LDS_ROW*2 + c*16), Ah + (long long)r*lda + k0 + c*8);
        }
        for (int e = tid; e < TN*8; e += 256) {
            int r = e >> 3, c = e & 7;
            cp16(base + 2*OA + (u32)(r*LDS_ROW*2 + c*16), Bh + (long long)r*ldb + k0 + c*8);
        }
    };

    float acc[MT][NT][4];
    #pragma unroll
    for (int i = 0; i < MT; i++)
        #pragma unroll
        for (int j = 0; j < NT; j++)
            #pragma unroll
            for (int q = 0; q < 4; q++) acc[i][j][q] = 0.f;

    load_tile(0, 0); CP_COMMIT();

    for (int t = 0; t < T; ++t) {
        if (t + 1 < T) { load_tile((t+1) & 1, (t+1)*KT); CP_COMMIT(); CP_WAIT1(); }
        else           { CP_WAIT0(); }
        __syncthreads();

        int s = t & 1;
        u32 aB = sbase + s*STG*2;
        u32 bB = aB + 2*OA;

        #pragma unroll
        for (int ks = 0; ks < 4; ks++) {
            u32 aF[MT][4], bF[NT][2];
            #pragma unroll
            for (int mt = 0; mt < MT; mt++) {
                int row = warp_m*MT*16 + mt*16 + (lane & 15);
                u32 off = (u32)(row*LDS_ROW*2 + ks*32 + (lane >> 4)*16);
                ldmx4(aF[mt][0], aF[mt][1], aF[mt][2], aF[mt][3], aB + off);
            }
            #pragma unroll
            for (int nt = 0; nt < NT; nt++) {
                int row = warp_n*NT*8 + nt*8 + (lane & 7);
                u32 off = (u32)(row*LDS_ROW*2 + ks*32 + ((lane >> 3) & 1)*16);
                ldmx2(bF[nt][0], bF[nt][1], bB + off);
            }
            #pragma unroll
            for (int mt = 0; mt < MT; mt++)
                #pragma unroll
                for (int nt = 0; nt < NT; nt++)
                    mma16816(acc[mt][nt], aF[mt], bF[nt]);
        }
        __syncthreads();
    }

    // ---- epilogue (packed stores: lanes own (n, n+1) pairs) ----
    long long cb = bb*sCb + hh*sCh;
    #pragma unroll
    for (int mt = 0; mt < MT; mt++) {
        #pragma unroll
        for (int nt = 0; nt < NT; nt++) {
            int rr = m0 + warp_m*MT*16 + mt*16 + (lane >> 2);
            int nn = n0 + warp_n*NT*8 + nt*8 + (lane & 3)*2;
            #pragma unroll
            for (int half = 0; half < 2; half++) {
                int m = rr + half*8;
                long long crow = cb + (long long)m*ldc;
                float v[2];
                #pragma unroll
                for (int j = 0; j < 2; j++) {
                    float vv = acc[mt][nt][half*2 + j] * alpha;
                    int n = nn + j;
                    if (bias)  vv += bias[n];
                    if (resid) vv += resid[crow + n];
                    if (flags & FLAG_GELU) {
                        float tg = tanhf(0.7978845608028654f * (vv + 0.044715f*vv*vv*vv));
                        vv = 0.5f * vv * (1.f + tg);
                    }
                    v[j] = vv;
                }
                if (flags & FLAG_HALF) {
                    *reinterpret_cast<u32*>(Chi + crow + nn) = (u32)f2h(v[0]) | ((u32)f2h(v[1]) << 16);
                } else {
                    *reinterpret_cast<float2*>(Cf + crow + nn) = make_float2(v[0], v[1]);
                }
            }
        }
    }
}

// ---------------- LayerNorm -> single fp16 ----------------
__global__ void ln_half_kernel(const float* __restrict__ x,
                               const float* __restrict__ g,
                               const float* __restrict__ b,
                               u16* __restrict__ ohi)
{
    long long row = blockIdx.x;
    const float* xr = x + row * EE;
    __shared__ float red[256];
    int tid = threadIdx.x;

    float s = 0.f;
    for (int c = tid; c < EE; c += 256) s += xr[c];
    red[tid] = s; __syncthreads();
    for (int st = 128; st > 0; st >>= 1){ if (tid < st) red[tid] += red[tid+st]; __syncthreads(); }
    float mu = red[0] * (1.f/EE); __syncthreads();

    float v = 0.f;
    for (int c = tid; c < EE; c += 256){ float d = xr[c]-mu; v += d*d; }
    red[tid] = v; __syncthreads();
    for (int st = 128; st > 0; st >>= 1){ if (tid < st) red[tid] += red[tid+st]; __syncthreads(); }
    float inv = rsqrtf(red[0]*(1.f/EE) + LN_EPS); __syncthreads();

    for (int c = tid; c < EE; c += 256) {
        float o = (xr[c]-mu)*inv*g[c] + b[c];
        ohi[row*EE + c] = f2h(o);
    }
}

// ---------------- merged weight convert: 4 tensors in one launch ----------------
__global__ void cvt4_kernel(const float* __restrict__ s0, u16* __restrict__ d0, long long n0,
                            const float* __restrict__ s1, u16* __restrict__ d1, long long n1,
                            const float* __restrict__ s2, u16* __restrict__ d2, long long n2,
                            const float* __restrict__ s3, u16* __restrict__ d3, long long n3)
{
    long long i = ((long long)blockIdx.x * 256 + threadIdx.x) * 4;
    const float* src; u16* dst;
    if      (i < n0)           { src = s0;        dst = d0;        }
    else if (i < n0+n1)        { src = s1;  i -= n0;        dst = d1; }
    else if (i < n0+n1+n2)     { src = s2;  i -= n0+n1;     dst = d2; }
    else if (i < n0+n1+n2+n3)  { src = s3;  i -= n0+n1+n2;  dst = d3; }
    else return;
    float4 v = *reinterpret_cast<const float4*>(src + i);
    u16 h[4] = { f2h(v.x), f2h(v.y), f2h(v.z), f2h(v.w) };
    *reinterpret_cast<u64*>(dst + i) = *(u64*)h;
}

// ---------------- transpose V: qkv[b,s, 2E + h*64 + d] -> vt[(b,h), d, s] ----------------
__global__ void transpose_v(const u16* __restrict__ qh, u16* __restrict__ vth)
{
    __shared__ u16 th[32][33];
    int bh = blockIdx.z; int b = bh >> 4, h = bh & 15;
    int s0 = blockIdx.x * 32, d0 = blockIdx.y * 32;
    int tx = threadIdx.x, ty = threadIdx.y;
    #pragma unroll
    for (int i = 0; i < 4; i++) {
        int s = s0 + ty + i*8;
        long long src = ((long long)(b*SS + s))*(3*EE) + 2*EE + h*DH + d0 + tx;
        th[ty + i*8][tx] = qh[src];
    }
    __syncthreads();
    #pragma unroll
    for (int i = 0; i < 4; i++) {
        int d = d0 + ty + i*8;
        long long dst = ((long long)(bh*DH + d))*SS + s0 + tx;
        vth[dst] = th[tx][ty + i*8];
    }
}

// ---------------- warp-per-head causal softmax + att_weights ----------------
__global__ __launch_bounds__(256)
void softmax_attw(u16* __restrict__ ph, float* __restrict__ outw)
{
    int bq = blockIdx.x;
    int b = bq >> 10, q = bq & (SS-1);
    int tid = threadIdx.x, lane = tid & 31, w = tid >> 5;
    int Lw = ((q >> 7) + 1) << 7;
    __shared__ float aw[SS];
    for (int c = tid; c < SS; c += 256) aw[c] = 0.f;
    __syncthreads();

    for (int hh = w; hh < HH; hh += 8) {
        long long base = (((long long)(b*HH + hh)) << 20) | ((long long)q << 10);
        float vals[32];
        float mx = -1e30f;
        #pragma unroll
        for (int i = 0; i < 32; i++) {
            int c0 = i << 5;
            if (c0 <= q) {
                int c = c0 + lane;
                float v = (c <= q) ? h2f(ph[base + c]) : -1e30f;
                vals[i] = v;
                mx = fmaxf(mx, v);
            }
        }
        #pragma unroll
        for (int o = 16; o > 0; o >>= 1) mx = fmaxf(mx, __shfl_xor_sync(0xFFFFFFFFu, mx, o));

        float sum = 0.f;
        #pragma unroll
        for (int i = 0; i < 32; i++) {
            int c0 = i << 5;
            if (c0 <= q) {
                int c = c0 + lane;
                float e = (c <= q) ? __expf(vals[i] - mx) : 0.f;
                vals[i] = e;
                sum += e;
            }
        }
        #pragma unroll
        for (int o = 16; o > 0; o >>= 1) sum += __shfl_xor_sync(0xFFFFFFFFu, sum, o);
        float inv = 1.f / sum;

        #pragma unroll
        for (int i = 0; i < 32; i++) {
            int c0 = i << 5;
            if (c0 < Lw) {
                int c = c0 + lane;
                float p = (c <= q) ? vals[i]*inv : 0.f;
                ph[base + c] = f2h(p);
                if (p != 0.f) atomicAdd(&aw[c], p);
            }
        }
    }
    __syncthreads();
    long long ob = ((long long)bq) << 10;
    #pragma unroll
    for (int j = 0; j < 4; j++) {
        int c = tid + 256*j;
        outw[ob + c] = aw[c] * (1.f/HH);
    }
}

// ---------------- launch ----------------
extern "C" void kernel_launch(void* const* d_in, const int* in_sizes, int n_in,
                              void* d_out, int out_size)
{
    const float* x      = (const float*)d_in[0];
    const float* ln1_g  = (const float*)d_in[2];
    const float* ln1_b  = (const float*)d_in[3];
    const float* ln2_g  = (const float*)d_in[4];
    const float* ln2_b  = (const float*)d_in[5];
    const float* w_in   = (const float*)d_in[6];
    const float* b_in   = (const float*)d_in[7];
    const float* w_out  = (const float*)d_in[8];
    const float* b_out  = (const float*)d_in[9];
    const float* w_fc   = (const float*)d_in[10];
    const float* b_fc   = (const float*)d_in[11];
    const float* w_proj = (const float*)d_in[12];
    const float* b_proj = (const float*)d_in[13];

    float* out_x = (float*)d_out;
    float* out_w = (float*)d_out + (long long)ROWS*EE;

    u16 *h_hi,*qkv_hi,*vt_hi,*p_hi,*att_hi,*h2_hi,*fc_hi;
    u16 *win_h,*wout_h,*wfc_h,*wpr_h;
    float *x1;
    cudaGetSymbolAddress((void**)&h_hi, g_h_hi);
    cudaGetSymbolAddress((void**)&qkv_hi, g_qkv_hi);
    cudaGetSymbolAddress((void**)&vt_hi, g_vt_hi);
    cudaGetSymbolAddress((void**)&p_hi, g_p_hi);
    cudaGetSymbolAddress((void**)&att_hi, g_att_hi);
    cudaGetSymbolAddress((void**)&x1, g_x1);
    cudaGetSymbolAddress((void**)&h2_hi, g_h2_hi);
    cudaGetSymbolAddress((void**)&fc_hi, g_fc_hi);
    cudaGetSymbolAddress((void**)&win_h, g_win_h);
    cudaGetSymbolAddress((void**)&wout_h, g_wout_h);
    cudaGetSymbolAddress((void**)&wfc_h, g_wfc_h);
    cudaGetSymbolAddress((void**)&wpr_h, g_wpr_h);

    const int SM128 = 2 * (TM*LDS_ROW + 128*LDS_ROW) * 2;   // 73728
    const int SM64  = 2 * (TM*LDS_ROW + 64*LDS_ROW) * 2;    // 55296
    cudaFuncSetAttribute((const void*)mma_gemm<128>, cudaFuncAttributeMaxDynamicSharedMemorySize, SM128);
    cudaFuncSetAttribute((const void*)mma_gemm<64>,  cudaFuncAttributeMaxDynamicSharedMemorySize, SM64);

    const long long SSS = (long long)SS*SS;

    // 0) convert all weights -> fp16 (single launch)
    {
        long long n0 = 3LL*EE*EE, n1 = (long long)EE*EE, n2 = 4LL*EE*EE, n3 = 4LL*EE*EE;
        long long chunks = (n0+n1+n2+n3)/4;
        cvt4_kernel<<<(int)((chunks + 255)/256), 256>>>(
            w_in, win_h, n0, w_out, wout_h, n1, w_fc, wfc_h, n2, w_proj, wpr_h, n3);
    }

    // 1) LN1 -> fp16
    ln_half_kernel<<<ROWS, 256>>>(x, ln1_g, ln1_b, h_hi);

    // 2) QKV = h @ w_in^T + b_in -> fp16
    mma_gemm<128><<<dim3(24, 32, 1), 256, SM128>>>(
        h_hi, EE, 0, 0,
        win_h, EE, 0, 0,
        nullptr, qkv_hi, 3*EE, 0, 0,
        b_in, nullptr, EE, 1, 1.f, FLAG_HALF);

    // 3) V transpose
    transpose_v<<<dim3(SS/32, DH/32, BB*HH), dim3(32,8)>>>(qkv_hi, vt_hi);

    // 4) scores = 0.125 * q @ k^T (masked tiles skipped) -> fp16
    mma_gemm<128><<<dim3(8, 8, BB*HH), 256, SM128>>>(
        qkv_hi, 3*EE, (long long)SS*3*EE, DH,
        qkv_hi + EE, 3*EE, (long long)SS*3*EE, DH,
        nullptr, p_hi, SS, (long long)HH*SSS, SSS,
        nullptr, nullptr, DH, HH, 0.125f, FLAG_CAUSAL | FLAG_HALF);

    // 5+6) warp-per-head softmax + att_weights (in-place fp16 probs)
    softmax_attw<<<ROWS, 256>>>(p_hi, out_w);

    // 7) att = P @ V^T (K clipped causally) -> fp16
    mma_gemm<64><<<dim3(1, 8, BB*HH), 256, SM64>>>(
        p_hi, SS, (long long)HH*SSS, SSS,
        vt_hi, SS, (long long)HH*DH*SS, (long long)DH*SS,
        nullptr, att_hi, EE, (long long)SS*EE, DH,
        nullptr, nullptr, SS, HH, 1.f, FLAG_CLIPK | FLAG_HALF);

    // 8) x1 = x + att @ w_out^T + b_out (f32 out)
    mma_gemm<128><<<dim3(8, 32, 1), 256, SM128>>>(
        att_hi, EE, 0, 0,
        wout_h, EE, 0, 0,
        x1, nullptr, EE, 0, 0,
        b_out, x, EE, 1, 1.f, 0);

    // 9) LN2 -> fp16
    ln_half_kernel<<<ROWS, 256>>>(x1, ln2_g, ln2_b, h2_hi);

    // 10) fc = gelu(h2 @ w_fc^T + b_fc) -> fp16
    mma_gemm<128><<<dim3(32, 32, 1), 256, SM128>>>(
        h2_hi, EE, 0, 0,
        wfc_h, EE, 0, 0,
        nullptr, fc_hi, 4*EE, 0, 0,
        b_fc, nullptr, EE, 1, 1.f, FLAG_HALF | FLAG_GELU);

    // 11) out_x = x1 + fc @ w_proj^T + b_proj (f32 out)
    mma_gemm<128><<<dim3(8, 32, 1), 256, SM128>>>(
        fc_hi, 4*EE, 0, 0,
        wpr_h, 4*EE, 0, 0,
        out_x, nullptr, EE, 0, 0,
        b_proj, x1, 4*EE, 1, 1.f, 0);
}